// round 14
// baseline (speedup 1.0000x reference)
#include <cuda_runtime.h>
#include <cuda_bf16.h>
#include <math.h>
#include <stdint.h>

#define BB 4
#define SEQ 4096
#define DMODEL 1024
#define NHEAD 16
#define HD 64
#define MF 256
#define DFF 4096
#define ROWS (BB*SEQ)
#define BH (BB*NHEAD)
#define NCHUNK 8
#define D3 (3*DMODEL)

#define DATA_NORM 0.35355339059327373f
#define RATIO     0.0625f
#define KEPS      1e-4f
#define LNEPS     1e-5f

// ---------------- scratch ----------------
__device__ float g_QKV[(size_t)ROWS*D3];
__device__ float g_bqkv[D3];
__device__ float g_Qp[(size_t)BH*SEQ*MF];
__device__ float g_Kp[(size_t)BH*SEQ*MF];
__device__ float g_kdiag[(size_t)BH*SEQ];
__device__ float g_kmax[BH];
__device__ float g_kvpart[(size_t)BH*NCHUNK*MF*HD];
__device__ float g_kspart[(size_t)BH*NCHUNK*MF];
__device__ float g_kv[(size_t)BH*MF*HD];
__device__ float g_ksum[BH*MF];
__device__ float g_attn[(size_t)ROWS*DMODEL];
__device__ float g_x1[(size_t)ROWS*DMODEL];
__device__ float g_t[(size_t)ROWS*DMODEL];
__device__ uint32_t g_projhi[HD*MF];
__device__ uint32_t g_projlo[HD*MF];

// bf16 hi/lo operands
__device__ __nv_bfloat16 g_xh[(size_t)ROWS*DMODEL],  g_xl[(size_t)ROWS*DMODEL];
__device__ __nv_bfloat16 g_ah[(size_t)ROWS*DMODEL],  g_al[(size_t)ROWS*DMODEL];
__device__ __nv_bfloat16 g_x1h[(size_t)ROWS*DMODEL], g_x1l[(size_t)ROWS*DMODEL];
__device__ __nv_bfloat16 g_hh[(size_t)ROWS*DFF],     g_hl[(size_t)ROWS*DFF];
__device__ __nv_bfloat16 g_wqkvTh[(size_t)D3*DMODEL], g_wqkvTl[(size_t)D3*DMODEL];
__device__ __nv_bfloat16 g_woTh[DMODEL*DMODEL],  g_woTl[DMODEL*DMODEL];
__device__ __nv_bfloat16 g_w1Th[(size_t)DFF*DMODEL], g_w1Tl[(size_t)DFF*DMODEL];
__device__ __nv_bfloat16 g_w2Th[(size_t)DMODEL*DFF], g_w2Tl[(size_t)DMODEL*DFF];

// ---------------- helpers ----------------
__device__ __forceinline__ float geluf(float x) {
    return 0.5f * x * (1.f + erff(x * 0.7071067811865476f));
}
__device__ __forceinline__ void atomicMaxF(float* addr, float v) {
    int old = __float_as_int(*addr);
    while (__int_as_float(old) < v) {
        int prev = atomicCAS((int*)addr, old, __float_as_int(v));
        if (prev == old) break;
        old = prev;
    }
}
__device__ __forceinline__ uint32_t f2tf(float f) {
    uint32_t r;
    asm("cvt.rna.tf32.f32 %0, %1;" : "=r"(r) : "f"(f));
    return r;
}
__device__ __forceinline__ float trunctf(float f) {
    return __uint_as_float(__float_as_uint(f) & 0xffffe000u);
}
__device__ __forceinline__ void mma16n8k8(float* c, const uint32_t* a, const uint32_t* b) {
    asm volatile(
        "mma.sync.aligned.m16n8k8.row.col.f32.tf32.tf32.f32 "
        "{%0,%1,%2,%3}, {%4,%5,%6,%7}, {%8,%9}, {%0,%1,%2,%3};"
        : "+f"(c[0]), "+f"(c[1]), "+f"(c[2]), "+f"(c[3])
        : "r"(a[0]), "r"(a[1]), "r"(a[2]), "r"(a[3]), "r"(b[0]), "r"(b[1]));
}
__device__ __forceinline__ void mma_bf16(float* c, const uint32_t* a, const uint32_t* b) {
    asm volatile(
        "mma.sync.aligned.m16n8k16.row.col.f32.bf16.bf16.f32 "
        "{%0,%1,%2,%3}, {%4,%5,%6,%7}, {%8,%9}, {%0,%1,%2,%3};"
        : "+f"(c[0]), "+f"(c[1]), "+f"(c[2]), "+f"(c[3])
        : "r"(a[0]), "r"(a[1]), "r"(a[2]), "r"(a[3]), "r"(b[0]), "r"(b[1]));
}
__device__ __forceinline__ void ldsm4(uint32_t* r, uint32_t addr) {
    asm volatile("ldmatrix.sync.aligned.m8n8.x4.shared.b16 {%0,%1,%2,%3}, [%4];"
        : "=r"(r[0]), "=r"(r[1]), "=r"(r[2]), "=r"(r[3]) : "r"(addr));
}
__device__ __forceinline__ void cpasync16(void* s, const void* g) {
    uint32_t saddr = (uint32_t)__cvta_generic_to_shared(s);
    asm volatile("cp.async.cg.shared.global [%0], [%1], 16;" :: "r"(saddr), "l"(g));
}
__device__ __forceinline__ void cpasync16a(uint32_t saddr, const void* g) {
    asm volatile("cp.async.cg.shared.global [%0], [%1], 16;" :: "r"(saddr), "l"(g));
}
__device__ __forceinline__ void cpcommit() { asm volatile("cp.async.commit_group;"); }
__device__ __forceinline__ void cpwait0()  { asm volatile("cp.async.wait_group 0;"); }
__device__ __forceinline__ void cpwait1()  { asm volatile("cp.async.wait_group 1;"); }

__device__ __forceinline__ void split_bf(float v, __nv_bfloat16& h, __nv_bfloat16& l) {
    h = __float2bfloat16_rn(v);
    l = __float2bfloat16_rn(v - __bfloat162float(h));
}

// ---------------- conversions ----------------
__global__ __launch_bounds__(256) void conv_act(
    const float* __restrict__ src, __nv_bfloat16* __restrict__ hi,
    __nv_bfloat16* __restrict__ lo, int n4)
{
    int i = blockIdx.x * 256 + threadIdx.x;
    if (i >= n4) return;
    float4 v = ((const float4*)src)[i];
    __nv_bfloat16 h0,h1,h2,h3,l0,l1,l2,l3;
    split_bf(v.x,h0,l0); split_bf(v.y,h1,l1); split_bf(v.z,h2,l2); split_bf(v.w,h3,l3);
    __nv_bfloat162 hp0 = {h0,h1}, hp1 = {h2,h3}, lp0 = {l0,l1}, lp1 = {l2,l3};
    uint2 hu = {*(uint32_t*)&hp0, *(uint32_t*)&hp1};
    uint2 lu = {*(uint32_t*)&lp0, *(uint32_t*)&lp1};
    ((uint2*)hi)[i] = hu;
    ((uint2*)lo)[i] = lu;
}
// weight [K,N] fp32 -> [N,K] bf16 hi/lo (transposed)
__global__ __launch_bounds__(256) void wt_conv(
    const float* __restrict__ src, __nv_bfloat16* __restrict__ hi,
    __nv_bfloat16* __restrict__ lo, int K, int N)
{
    __shared__ float tile[32][33];
    int n0 = blockIdx.x * 32, k0 = blockIdx.y * 32;
    int tid = threadIdx.x;
    int c = tid & 31, r0 = (tid >> 5) * 4;
    #pragma unroll
    for (int rr = 0; rr < 4; rr++)
        tile[r0 + rr][c] = src[(size_t)(k0 + r0 + rr) * N + n0 + c];
    __syncthreads();
    int j = tid & 31, i0 = (tid >> 5) * 4;
    #pragma unroll
    for (int ii = 0; ii < 4; ii++) {
        float v = tile[j][i0 + ii];
        __nv_bfloat16 h, l;
        split_bf(v, h, l);
        size_t o = (size_t)(n0 + i0 + ii) * K + k0 + j;
        hi[o] = h; lo[o] = l;
    }
}
__global__ void pack_bias(const float* bq, const float* bk, const float* bv) {
    int i = blockIdx.x * 256 + threadIdx.x;
    if (i < DMODEL) {
        g_bqkv[i] = bq[i];
        g_bqkv[1024 + i] = bk[i];
        g_bqkv[2048 + i] = bv[i];
    }
}

// ---------------- bf16 3-term GEMM: 128x128xBK32, 3-stage, swizzled ldmatrix ----------------
#define GS_AH 0
#define GS_AL 8192
#define GS_BH 16384
#define GS_BL 24576
#define GS_STAGE 32768
#define GEMM_SMEM (3*GS_STAGE)    // 98304 B

__global__ __launch_bounds__(256, 2) void bf16_gemm(
    const __nv_bfloat16* __restrict__ Ah_, const __nv_bfloat16* __restrict__ Al_,
    const __nv_bfloat16* __restrict__ Bh_, const __nv_bfloat16* __restrict__ Bl_,
    const float* __restrict__ bias, float* __restrict__ Cf,
    __nv_bfloat16* __restrict__ Ch, __nv_bfloat16* __restrict__ Cl,
    int M, int N, int K, int mode)
{
    extern __shared__ char gsm[];
    uint32_t sb = (uint32_t)__cvta_generic_to_shared(gsm);

    int tid = threadIdx.x, lane = tid & 31, wid = tid >> 5;
    int warp_m = wid & 3, warp_n = wid >> 2;   // 4x2, warp tile 32x64
    int row0 = blockIdx.y * 128, col0 = blockIdx.x * 128;

    // loader: u = tid + i*256 -> row = u>>2 (0..127 via i), chunk c = u&3 (8 bf16 each)
    int lrow = tid >> 2, lc = tid & 3;

    // ldmatrix per-thread: A rows, B rows
    int aR = warp_m * 32 + (lane & 15);        // +16 for am=1
    int aKh = lane >> 4;                        // 0/1 -> +8 bf16
    int bN  = warp_n * 64 + (lane & 7) + ((lane >> 4) & 1) * 8;  // +16*p
    int bKh = (lane >> 3) & 1;

    float acc[2][8][4];
    #pragma unroll
    for (int i = 0; i < 2; i++)
        #pragma unroll
        for (int j = 0; j < 8; j++)
            #pragma unroll
            for (int l = 0; l < 4; l++) acc[i][j][l] = 0.f;

    int nk = K >> 5;

#define LOAD_STAGE(kt, st)                                                            \
    {                                                                                 \
        uint32_t stb = sb + (st) * GS_STAGE;                                          \
        int kc = (kt) * 32;                                                           \
        _Pragma("unroll")                                                             \
        for (int i = 0; i < 2; i++) {                                                 \
            int row = lrow + i * 64;                                                  \
            uint32_t so = (uint32_t)(row * 64 + ((lc ^ ((row >> 1) & 3)) << 4));      \
            size_t go = (size_t)(row0 + row) * K + kc + lc * 8;                       \
            cpasync16a(stb + GS_AH + so, Ah_ + go);                                   \
            cpasync16a(stb + GS_AL + so, Al_ + go);                                   \
            size_t gb = (size_t)(col0 + row) * K + kc + lc * 8;                       \
            cpasync16a(stb + GS_BH + so, Bh_ + gb);                                   \
            cpasync16a(stb + GS_BL + so, Bl_ + gb);                                   \
        }                                                                             \
    }

    LOAD_STAGE(0, 0); cpcommit();
    LOAD_STAGE(1, 1); cpcommit();

    for (int kt = 0; kt < nk; kt++) {
        int cur = kt % 3;
        cpwait1();
        __syncthreads();

        if (kt + 2 < nk) LOAD_STAGE(kt + 2, (kt + 2) % 3);
        cpcommit();

        uint32_t stb = sb + cur * GS_STAGE;

        #pragma unroll
        for (int kh = 0; kh < 2; kh++) {
            int kc0 = kh * 2;   // 16-bf16 chunk start, in 8-bf16 units

            uint32_t ahf[2][4], alf[2][4], bhf[4][4], blf[4][4];
            #pragma unroll
            for (int am = 0; am < 2; am++) {
                int r = aR + am * 16;
                uint32_t ad = stb + (uint32_t)(r * 64 + ((((kc0 + aKh) ^ ((r >> 1) & 3))) << 4));
                ldsm4(ahf[am], ad + GS_AH);
                ldsm4(alf[am], ad + GS_AL);
            }
            #pragma unroll
            for (int p = 0; p < 4; p++) {
                int n = bN + p * 16;
                uint32_t bd = stb + (uint32_t)(n * 64 + ((((kc0 + bKh) ^ ((n >> 1) & 3))) << 4));
                ldsm4(bhf[p], bd + GS_BH);
                ldsm4(blf[p], bd + GS_BL);
            }
            #pragma unroll
            for (int am = 0; am < 2; am++)
                #pragma unroll
                for (int t = 0; t < 8; t++) {
                    const uint32_t* bh2 = &bhf[t >> 1][2 * (t & 1)];
                    const uint32_t* bl2 = &blf[t >> 1][2 * (t & 1)];
                    mma_bf16(acc[am][t], ahf[am], bh2);
                    mma_bf16(acc[am][t], alf[am], bh2);
                    mma_bf16(acc[am][t], ahf[am], bl2);
                }
        }
        // no bottom barrier: next top barrier orders reads before overwrite
    }
#undef LOAD_STAGE

    #pragma unroll
    for (int am = 0; am < 2; am++) {
        int r = row0 + warp_m * 32 + am * 16 + (lane >> 2);
        #pragma unroll
        for (int t = 0; t < 8; t++) {
            int c = col0 + warp_n * 64 + t * 8 + (lane & 3) * 2;
            float2 bv = *(const float2*)(bias + c);
            float v0 = acc[am][t][0] + bv.x;
            float v1 = acc[am][t][1] + bv.y;
            float v2 = acc[am][t][2] + bv.x;
            float v3 = acc[am][t][3] + bv.y;
            if (mode == 0) {
                float2 w0 = {v0, v1}, w1 = {v2, v3};
                *(float2*)(Cf + (size_t)r * N + c)       = w0;
                *(float2*)(Cf + (size_t)(r + 8) * N + c) = w1;
            } else {
                v0 = geluf(v0); v1 = geluf(v1); v2 = geluf(v2); v3 = geluf(v3);
                __nv_bfloat16 h0,h1,h2,h3,l0,l1,l2,l3;
                split_bf(v0,h0,l0); split_bf(v1,h1,l1); split_bf(v2,h2,l2); split_bf(v3,h3,l3);
                __nv_bfloat162 hp0={h0,h1}, hp1={h2,h3}, lp0={l0,l1}, lp1={l2,l3};
                *(uint32_t*)(Ch + (size_t)r * N + c)       = *(uint32_t*)&hp0;
                *(uint32_t*)(Ch + (size_t)(r + 8) * N + c) = *(uint32_t*)&hp1;
                *(uint32_t*)(Cl + (size_t)r * N + c)       = *(uint32_t*)&lp0;
                *(uint32_t*)(Cl + (size_t)(r + 8) * N + c) = *(uint32_t*)&lp1;
            }
        }
    }
}

// ---------------- proj prep ----------------
__global__ void prep_proj(const float* __restrict__ proj) {
    int i = blockIdx.x * 256 + threadIdx.x;
    if (i < HD * MF) {
        int d = i >> 8, m = i & 255;
        float v = proj[m * HD + d];
        uint32_t h = f2tf(v);
        g_projhi[i] = h;
        g_projlo[i] = f2tf(v - __uint_as_float(h));
    }
}
__global__ void kmax_init() { if (threadIdx.x < BH) g_kmax[threadIdx.x] = -3.4e38f; }

// ---------------- fused dash ----------------
#define DPH_OFF 0
#define DPL_OFF 67584
#define DAH_OFF 135168
#define DAL_OFF 143872
#define DSD_OFF 152576
#define DSM_OFF 152704
#define DWM_OFF 152832
#define DASH_SMEM 153856

extern "C" __global__ __launch_bounds__(256) void dash_fused(
    const float* __restrict__ data, int ldd, float* __restrict__ outp,
    float* __restrict__ kdiag, float* __restrict__ kmaxbuf, int isquery)
{
    extern __shared__ unsigned char dsm[];
    uint32_t (*Ph)[264] = (uint32_t(*)[264])(dsm + DPH_OFF);
    uint32_t (*Pl)[264] = (uint32_t(*)[264])(dsm + DPL_OFF);
    uint32_t (*Ah)[68]  = (uint32_t(*)[68])(dsm + DAH_OFF);
    uint32_t (*Al)[68]  = (uint32_t(*)[68])(dsm + DAL_OFF);
    float* sdiag = (float*)(dsm + DSD_OFF);
    float* smax  = (float*)(dsm + DSM_OFF);
    float* wmax  = (float*)(dsm + DWM_OFF);

    int bh = blockIdx.y, b = bh >> 4, h = bh & 15;
    int n0 = blockIdx.x * 32;
    int tid = threadIdx.x, lane = tid & 31, wid = tid >> 5;

    #pragma unroll
    for (int i = 0; i < 16; i++) {
        int cid = i * 256 + tid;
        int r = cid >> 6, c = (cid & 63) * 4;
        cpasync16(&Ph[r][c], g_projhi + r * 256 + c);
        cpasync16(&Pl[r][c], g_projlo + r * 256 + c);
    }
    cpcommit();

    {
        int r = tid >> 3, c0 = (tid & 7) * 8;
        const float* src = data + ((size_t)(b * SEQ + n0 + r)) * ldd + h * HD + c0;
        float4 v0 = *(const float4*)src;
        float4 v1 = *(const float4*)(src + 4);
        float ss = v0.x*v0.x + v0.y*v0.y + v0.z*v0.z + v0.w*v0.w
                 + v1.x*v1.x + v1.y*v1.y + v1.z*v1.z + v1.w*v1.w;
        ss += __shfl_xor_sync(~0u, ss, 1);
        ss += __shfl_xor_sync(~0u, ss, 2);
        ss += __shfl_xor_sync(~0u, ss, 4);
        if ((tid & 7) == 0) sdiag[r] = 0.0625f * ss;
        float a[8] = {v0.x,v0.y,v0.z,v0.w,v1.x,v1.y,v1.z,v1.w};
        #pragma unroll
        for (int j = 0; j < 8; j++) {
            float av = DATA_NORM * a[j];
            uint32_t hi = f2tf(av);
            Ah[r][c0+j] = hi;
            Al[r][c0+j] = f2tf(av - __uint_as_float(hi));
        }
    }
    cpwait0();
    __syncthreads();

    float acc[2][4][4];
    #pragma unroll
    for (int i = 0; i < 2; i++)
        #pragma unroll
        for (int j = 0; j < 4; j++)
            #pragma unroll
            for (int l = 0; l < 4; l++) acc[i][j][l] = 0.f;

    int ncol = wid * 32;
    for (int k0 = 0; k0 < 64; k0 += 8) {
        uint32_t ah[2][4], al[2][4];
        #pragma unroll
        for (int mt = 0; mt < 2; mt++) {
            int r = mt * 16 + (lane >> 2), c = k0 + (lane & 3);
            ah[mt][0] = Ah[r][c];    ah[mt][1] = Ah[r+8][c];
            ah[mt][2] = Ah[r][c+4];  ah[mt][3] = Ah[r+8][c+4];
            al[mt][0] = Al[r][c];    al[mt][1] = Al[r+8][c];
            al[mt][2] = Al[r][c+4];  al[mt][3] = Al[r+8][c+4];
        }
        uint32_t bhf[4][2], blf[4][2];
        #pragma unroll
        for (int nt = 0; nt < 4; nt++) {
            int n = ncol + nt * 8 + (lane >> 2), kk = k0 + (lane & 3);
            bhf[nt][0] = Ph[kk][n];   bhf[nt][1] = Ph[kk+4][n];
            blf[nt][0] = Pl[kk][n];   blf[nt][1] = Pl[kk+4][n];
        }
        #pragma unroll
        for (int mt = 0; mt < 2; mt++)
            #pragma unroll
            for (int nt = 0; nt < 4; nt++) {
                mma16n8k8(acc[mt][nt], ah[mt], bhf[nt]);
                mma16n8k8(acc[mt][nt], ah[mt], blf[nt]);
                mma16n8k8(acc[mt][nt], al[mt], bhf[nt]);
            }
    }

    #pragma unroll
    for (int mt = 0; mt < 2; mt++) {
        float m0 = -3.4e38f, m1 = -3.4e38f;
        #pragma unroll
        for (int nt = 0; nt < 4; nt++) {
            m0 = fmaxf(m0, fmaxf(acc[mt][nt][0], acc[mt][nt][1]));
            m1 = fmaxf(m1, fmaxf(acc[mt][nt][2], acc[mt][nt][3]));
        }
        m0 = fmaxf(m0, __shfl_xor_sync(~0u, m0, 1));
        m0 = fmaxf(m0, __shfl_xor_sync(~0u, m0, 2));
        m1 = fmaxf(m1, __shfl_xor_sync(~0u, m1, 1));
        m1 = fmaxf(m1, __shfl_xor_sync(~0u, m1, 2));
        if ((lane & 3) == 0) {
            wmax[wid * 32 + mt * 16 + (lane >> 2)]     = m0;
            wmax[wid * 32 + mt * 16 + 8 + (lane >> 2)] = m1;
        }
    }
    __syncthreads();
    if (tid < 32) {
        float mx = wmax[tid];
        #pragma unroll
        for (int w = 1; w < 8; w++) mx = fmaxf(mx, wmax[w * 32 + tid]);
        smax[tid] = mx;
    }
    __syncthreads();
    if (!isquery) {
        if (tid < 32) kdiag[(size_t)bh * SEQ + n0 + tid] = sdiag[tid];
        if (tid == 0) {
            float bm = smax[0];
            #pragma unroll
            for (int i = 1; i < 32; i++) bm = fmaxf(bm, smax[i]);
            atomicMaxF(&kmaxbuf[bh], bm);
        }
    }

    #pragma unroll
    for (int mt = 0; mt < 2; mt++) {
        int r = mt * 16 + (lane >> 2);
        #pragma unroll
        for (int nt = 0; nt < 4; nt++) {
            int c = ncol + nt * 8 + (lane & 3) * 2;
            float v0 = acc[mt][nt][0], v1 = acc[mt][nt][1];
            float v2 = acc[mt][nt][2], v3 = acc[mt][nt][3];
            if (isquery) {
                float s0 = sdiag[r] + smax[r];
                float s1 = sdiag[r+8] + smax[r+8];
                v0 = RATIO * (__expf(v0 - s0) + KEPS);
                v1 = RATIO * (__expf(v1 - s0) + KEPS);
                v2 = RATIO * (__expf(v2 - s1) + KEPS);
                v3 = RATIO * (__expf(v3 - s1) + KEPS);
            }
            float2 w0 = {v0, v1}, w1 = {v2, v3};
            *(float2*)(outp + ((size_t)bh * SEQ + n0 + r) * MF + c)     = w0;
            *(float2*)(outp + ((size_t)bh * SEQ + n0 + r + 8) * MF + c) = w1;
        }
    }
}

// ---------------- kv + ksum ----------------
#define KAS_OFF 0
#define KVS_OFF 40960
#define KSR_OFF 50176
#define KV_SMEM 54272

extern "C" __global__ __launch_bounds__(256) void kv_ksum_kernel(
    const float* __restrict__ Kraw, const float* __restrict__ V, int ldv)
{
    extern __shared__ unsigned char ksm[];
    float (*As)[256][20] = (float(*)[256][20])(ksm + KAS_OFF);
    float (*Vs)[16][72]  = (float(*)[16][72])(ksm + KVS_OFF);
    float (*sred)[256]   = (float(*)[256])(ksm + KSR_OFF);

    int bh = blockIdx.y, chunk = blockIdx.x;
    int b = bh >> 4, h = bh & 15;
    int tid = threadIdx.x, lane = tid & 31, wid = tid >> 5;
    int wm = wid & 3, wn = wid >> 2;

    float kmax = g_kmax[bh];
    const float* Kb  = Kraw + ((size_t)bh * SEQ + chunk * 512) * MF;
    const float* Vb  = V + ((size_t)(b * SEQ + chunk * 512)) * ldv + h * HD;
    const float* dgb = g_kdiag + (size_t)bh * SEQ + chunk * 512;

    int mcol = tid & 63;
    int nr   = tid >> 6;
    float ks[4] = {0.f, 0.f, 0.f, 0.f};

    float acc[4][4][4];
    #pragma unroll
    for (int i = 0; i < 4; i++)
        #pragma unroll
        for (int j = 0; j < 4; j++)
            #pragma unroll
            for (int l = 0; l < 4; l++) acc[i][j][l] = 0.f;

#define LOAD_TILE(nt, buf)                                                        \
    {                                                                             \
        _Pragma("unroll")                                                         \
        for (int p = 0; p < 4; p++) {                                             \
            int nl = p * 4 + nr;                                                  \
            int ng = (nt) * 16 + nl;                                              \
            float dg = dgb[ng] + kmax;                                            \
            const float* kr = Kb + (size_t)ng * MF + mcol;                        \
            float r0 = kr[0], r1 = kr[64], r2 = kr[128], r3 = kr[192];            \
            float e0 = trunctf(RATIO * (__expf(r0 - dg) + KEPS));                 \
            float e1 = trunctf(RATIO * (__expf(r1 - dg) + KEPS));                 \
            float e2 = trunctf(RATIO * (__expf(r2 - dg) + KEPS));                 \
            float e3 = trunctf(RATIO * (__expf(r3 - dg) + KEPS));                 \
            ks[0] += e0; ks[1] += e1; ks[2] += e2; ks[3] += e3;                   \
            As[buf][mcol][nl] = e0;   As[buf][mcol+64][nl] = e1;                  \
            As[buf][mcol+128][nl] = e2; As[buf][mcol+192][nl] = e3;               \
        }                                                                         \
        cpasync16(&Vs[buf][tid >> 4][(tid & 15) * 4],                             \
                  Vb + (size_t)((nt) * 16 + (tid >> 4)) * ldv + (tid & 15) * 4);  \
        cpcommit();                                                               \
    }

    LOAD_TILE(0, 0);

    for (int nt = 0; nt < 32; nt++) {
        int buf = nt & 1;
        cpwait0();
        __syncthreads();
        if (nt + 1 < 32) LOAD_TILE(nt + 1, buf ^ 1);

        const uint32_t (*Au)[20] = (const uint32_t(*)[20])As[buf];
        const uint32_t (*Vu)[72] = (const uint32_t(*)[72])Vs[buf];

        #pragma unroll
        for (int ks2 = 0; ks2 < 2; ks2++) {
            int k0 = ks2 * 8;
            uint32_t a[4][4];
            #pragma unroll
            for (int mt = 0; mt < 4; mt++) {
                int r = wm * 64 + mt * 16 + (lane >> 2), c = k0 + (lane & 3);
                a[mt][0] = Au[r][c];
                a[mt][1] = Au[r+8][c];
                a[mt][2] = Au[r][c+4];
                a[mt][3] = Au[r+8][c+4];
            }
            uint32_t bb[4][2];
            #pragma unroll
            for (int dt = 0; dt < 4; dt++) {
                int n = wn * 32 + dt * 8 + (lane >> 2), kk = k0 + (lane & 3);
                bb[dt][0] = Vu[kk][n];
                bb[dt][1] = Vu[kk+4][n];
            }
            #pragma unroll
            for (int mt = 0; mt < 4; mt++)
                #pragma unroll
                for (int dt = 0; dt < 4; dt++)
                    mma16n8k8(acc[mt][dt], a[mt], bb[dt]);
        }
    }
#undef LOAD_TILE

    float* kvp = g_kvpart + ((size_t)(bh * NCHUNK + chunk)) * MF * HD;
    #pragma unroll
    for (int mt = 0; mt < 4; mt++) {
        int m = wm * 64 + mt * 16 + (lane >> 2);
        #pragma unroll
        for (int dt = 0; dt < 4; dt++) {
            int d = wn * 32 + dt * 8 + (lane & 3) * 2;
            float2 w0 = {acc[mt][dt][0], acc[mt][dt][1]};
            float2 w1 = {acc[mt][dt][2], acc[mt][dt][3]};
            *(float2*)(kvp + (size_t)m * HD + d)       = w0;
            *(float2*)(kvp + (size_t)(m + 8) * HD + d) = w1;
        }
    }
    __syncthreads();
    sred[nr][mcol]       = ks[0];
    sred[nr][mcol + 64]  = ks[1];
    sred[nr][mcol + 128] = ks[2];
    sred[nr][mcol + 192] = ks[3];
    __syncthreads();
    float s = sred[0][tid & 255] + sred[1][tid & 255] + sred[2][tid & 255] + sred[3][tid & 255];
    g_kspart[(size_t)(bh * NCHUNK + chunk) * MF + tid] = s;
}

// ---------------- reduce partials ----------------
__global__ __launch_bounds__(256) void kv_reduce() {
    int bh = blockIdx.x, tid = threadIdx.x;
    for (int i = tid; i < MF * HD; i += 256) {
        float s = 0.f;
        #pragma unroll
        for (int c = 0; c < NCHUNK; c++)
            s += g_kvpart[((size_t)(bh * NCHUNK + c)) * MF * HD + i];
        g_kv[(size_t)bh * MF * HD + i] = s;
    }
    float s = 0.f;
    #pragma unroll
    for (int c = 0; c < NCHUNK; c++)
        s += g_kspart[(size_t)(bh * NCHUNK + c) * MF + tid];
    g_ksum[bh * MF + tid] = s;
}

// ---------------- attn + denom fused ----------------
__global__ __launch_bounds__(256) void attn_fused(
    const float* __restrict__ Qp, float* __restrict__ out)
{
    __shared__ float Qs[2][128][20];
    __shared__ float Bs[2][16][72];
    __shared__ float sk[256];
    __shared__ float sdn[128];

    int bh = blockIdx.y, b = bh >> 4, h = bh & 15;
    int n0 = blockIdx.x * 128;
    int tid = threadIdx.x, lane = tid & 31, wid = tid >> 5;
    int wm = wid & 3, wn = wid >> 2;

    sk[tid] = g_ksum[bh * MF + tid];

    const float* Qb = Qp + ((size_t)bh * SEQ + n0) * MF;
    const float* Vb = g_kv + (size_t)bh * MF * HD;

#define LOADQ(kt, buf)                                                        \
    {                                                                         \
        _Pragma("unroll")                                                     \
        for (int i = 0; i < 2; i++) {                                         \
            int cid = i * 256 + tid;                                          \
            int r = cid >> 2, c = (cid & 3) * 4;                              \
            cpasync16(&Qs[buf][r][c], Qb + (size_t)r * MF + (kt) * 16 + c);   \
        }                                                                     \
        cpasync16(&Bs[buf][tid >> 4][(tid & 15) * 4],                         \
                  Vb + (size_t)((kt) * 16 + (tid >> 4)) * HD + (tid & 15) * 4); \
        cpcommit();                                                           \
    }

    LOADQ(0, 0);

    float acc[2][4][4];
    #pragma unroll
    for (int i = 0; i < 2; i++)
        #pragma unroll
        for (int j = 0; j < 4; j++)
            #pragma unroll
            for (int l = 0; l < 4; l++) acc[i][j][l] = 0.f;
    float dn = 0.f;

    for (int kt = 0; kt < 16; kt++) {
        int buf = kt & 1;
        cpwait0();
        __syncthreads();
        if (kt + 1 < 16) LOADQ(kt + 1, buf ^ 1);

        if (tid < 128) {
            #pragma unroll
            for (int j = 0; j < 16; j++) dn += trunctf(Qs[buf][tid][j]) * sk[kt * 16 + j];
        }

        const uint32_t (*Qu)[20] = (const uint32_t(*)[20])Qs[buf];
        const uint32_t (*Bu)[72] = (const uint32_t(*)[72])Bs[buf];

        #pragma unroll
        for (int ks2 = 0; ks2 < 2; ks2++) {
            int k0 = ks2 * 8;
            uint32_t a[2][4];
            #pragma unroll
            for (int mt = 0; mt < 2; mt++) {
                int r = wm * 32 + mt * 16 + (lane >> 2), c = k0 + (lane & 3);
                a[mt][0] = Qu[r][c];
                a[mt][1] = Qu[r+8][c];
                a[mt][2] = Qu[r][c+4];
                a[mt][3] = Qu[r+8][c+4];
            }
            uint32_t bb[4][2];
            #pragma unroll
            for (int dt = 0; dt < 4; dt++) {
                int n = wn * 32 + dt * 8 + (lane >> 2), kk = k0 + (lane & 3);
                bb[dt][0] = Bu[kk][n];
                bb[dt][1] = Bu[kk+4][n];
            }
            #pragma unroll
            for (int mt = 0; mt < 2; mt++)
                #pragma unroll
                for (int dt = 0; dt < 4; dt++)
                    mma16n8k8(acc[mt][dt], a[mt], bb[dt]);
        }
    }
#undef LOADQ

    if (tid < 128) sdn[tid] = dn;
    __syncthreads();

    #pragma unroll
    for (int mt = 0; mt < 2; mt++) {
        int r = wm * 32 + mt * 16 + (lane >> 2);
        float i0 = 1.f / sdn[r];
        float i1 = 1.f / sdn[r + 8];
        #pragma unroll
        for (int dt = 0; dt < 4; dt++) {
            int c = wn * 32 + dt * 8 + (lane & 3) * 2;
            float2 w0 = {acc[mt][dt][0] * i0, acc[mt][dt][1] * i0};
            float2 w1 = {acc[mt][dt][2] * i1, acc[mt][dt][3] * i1};
            *(float2*)(out + ((size_t)(b * SEQ + n0 + r)) * DMODEL + h * HD + c)     = w0;
            *(float2*)(out + ((size_t)(b * SEQ + n0 + r + 8)) * DMODEL + h * HD + c) = w1;
        }
    }
}

// ---------------- fused residual + LayerNorm ----------------
__global__ __launch_bounds__(256) void ln_kernel(
    const float* __restrict__ a, const float* __restrict__ res,
    const float* __restrict__ gam, const float* __restrict__ bet, float* __restrict__ out)
{
    __shared__ float red[8];
    int row = blockIdx.x, tid = threadIdx.x;
    int lane = tid & 31, w = tid >> 5;
    size_t base = (size_t)row * DMODEL + tid * 4;
    float4 v = *(const float4*)(a + base);
    float4 r = *(const float4*)(res + base);
    v.x += r.x; v.y += r.y; v.z += r.z; v.w += r.w;

    float s = v.x + v.y + v.z + v.w;
    #pragma unroll
    for (int o = 16; o; o >>= 1) s += __shfl_xor_sync(0xffffffffu, s, o);
    if (lane == 0) red[w] = s;
    __syncthreads();
    float t = (tid < 8) ? red[tid] : 0.f;
    if (w == 0) {
        #pragma unroll
        for (int o = 4; o; o >>= 1) t += __shfl_xor_sync(0xffffffffu, t, o);
        if (lane == 0) red[0] = t;
    }
    __syncthreads();
    float mean = red[0] * (1.f / DMODEL);
    __syncthreads();

    float d0 = v.x - mean, d1 = v.y - mean, d2 = v.z - mean, d3 = v.w - mean;
    float s2 = d0*d0 + d1*d1 + d2*d2 + d3*d3;
    #pragma unroll
    for (int o = 16; o; o >>= 1) s2 += __shfl_xor_sync(0xffffffffu, s2, o);
    if (lane == 0) red[w] = s2;
    __syncthreads();
    float t2 = (tid < 8) ? red[tid] : 0.f;
    if (w == 0) {
        #pragma unroll
        for (int o = 4; o; o >>= 1) t2 += __shfl_xor_sync(0xffffffffu, t2, o);
        if (lane == 0) red[0] = t2;
    }
    __syncthreads();
    float var = red[0] * (1.f / DMODEL);
    float inv = rsqrtf(var + LNEPS);

    float4 g4 = *(const float4*)(gam + tid * 4);
    float4 b4 = *(const float4*)(bet + tid * 4);
    float4 o4;
    o4.x = d0 * inv * g4.x + b4.x;
    o4.y = d1 * inv * g4.y + b4.y;
    o4.z = d2 * inv * g4.z + b4.z;
    o4.w = d3 * inv * g4.w + b4.w;
    *(float4*)(out + base) = o4;
}

// ---------------- launch ----------------
extern "C" void kernel_launch(void* const* d_in, const int* in_sizes, int n_in,
                              void* d_out, int out_size)
{
    const float* x  = (const float*)d_in[0];
    const float* wq = (const float*)d_in[1];  const float* bq = (const float*)d_in[2];
    const float* wk = (const float*)d_in[3];  const float* bk = (const float*)d_in[4];
    const float* wv = (const float*)d_in[5];  const float* bv = (const float*)d_in[6];
    const float* wo = (const float*)d_in[7];  const float* bo = (const float*)d_in[8];
    const float* proj = (const float*)d_in[9];
    const float* w1 = (const float*)d_in[10]; const float* b1 = (const float*)d_in[11];
    const float* w2 = (const float*)d_in[12]; const float* b2 = (const float*)d_in[13];
    const float* ln1g = (const float*)d_in[14]; const float* ln1b = (const float*)d_in[15];
    const float* ln2g = (const float*)d_in[16]; const float* ln2b = (const float*)d_in[17];
    float* out = (float*)d_out;

    static int attr_done = 0;
    if (!attr_done) {
        cudaFuncSetAttribute(bf16_gemm, cudaFuncAttributeMaxDynamicSharedMemorySize, GEMM_SMEM);
        cudaFuncSetAttribute(dash_fused, cudaFuncAttributeMaxDynamicSharedMemorySize, DASH_SMEM);
        cudaFuncSetAttribute(kv_ksum_kernel, cudaFuncAttributeMaxDynamicSharedMemorySize, KV_SMEM);
        attr_done = 1;
    }

    float *QKV, *bqkv, *Qp, *Kp, *kdiag, *kmax, *attn, *x1, *t;
    cudaGetSymbolAddress((void**)&QKV, g_QKV);
    cudaGetSymbolAddress((void**)&bqkv, g_bqkv);
    cudaGetSymbolAddress((void**)&Qp, g_Qp);
    cudaGetSymbolAddress((void**)&Kp, g_Kp);
    cudaGetSymbolAddress((void**)&kdiag, g_kdiag);
    cudaGetSymbolAddress((void**)&kmax, g_kmax);
    cudaGetSymbolAddress((void**)&attn, g_attn);
    cudaGetSymbolAddress((void**)&x1, g_x1);
    cudaGetSymbolAddress((void**)&t,  g_t);

    __nv_bfloat16 *xh,*xl,*ah,*al,*x1h,*x1l,*hh,*hl;
    __nv_bfloat16 *wqkvTh,*wqkvTl,*woTh,*woTl,*w1Th,*w1Tl,*w2Th,*w2Tl;
    cudaGetSymbolAddress((void**)&xh, g_xh);   cudaGetSymbolAddress((void**)&xl, g_xl);
    cudaGetSymbolAddress((void**)&ah, g_ah);   cudaGetSymbolAddress((void**)&al, g_al);
    cudaGetSymbolAddress((void**)&x1h, g_x1h); cudaGetSymbolAddress((void**)&x1l, g_x1l);
    cudaGetSymbolAddress((void**)&hh, g_hh);   cudaGetSymbolAddress((void**)&hl, g_hl);
    cudaGetSymbolAddress((void**)&wqkvTh, g_wqkvTh); cudaGetSymbolAddress((void**)&wqkvTl, g_wqkvTl);
    cudaGetSymbolAddress((void**)&woTh, g_woTh); cudaGetSymbolAddress((void**)&woTl, g_woTl);
    cudaGetSymbolAddress((void**)&w1Th, g_w1Th); cudaGetSymbolAddress((void**)&w1Tl, g_w1Tl);
    cudaGetSymbolAddress((void**)&w2Th, g_w2Th); cudaGetSymbolAddress((void**)&w2Tl, g_w2Tl);

    prep_proj<<<64, 256>>>(proj);
    kmax_init<<<1, 64>>>();
    pack_bias<<<4, 256>>>(bq, bk, bv);

    // weight transpose + bf16 split
    wt_conv<<<dim3(32, 32), 256>>>(wq, wqkvTh,                wqkvTl,                DMODEL, DMODEL);
    wt_conv<<<dim3(32, 32), 256>>>(wk, wqkvTh + 1024*1024,    wqkvTl + 1024*1024,    DMODEL, DMODEL);
    wt_conv<<<dim3(32, 32), 256>>>(wv, wqkvTh + 2*1024*1024,  wqkvTl + 2*1024*1024,  DMODEL, DMODEL);
    wt_conv<<<dim3(32, 32), 256>>>(wo, woTh, woTl, DMODEL, DMODEL);
    wt_conv<<<dim3(DFF/32, DMODEL/32), 256>>>(w1, w1Th, w1Tl, DMODEL, DFF);
    wt_conv<<<dim3(DMODEL/32, DFF/32), 256>>>(w2, w2Th, w2Tl, DFF, DMODEL);
    conv_act<<<ROWS*DMODEL/4/256, 256>>>(x, xh, xl, ROWS*DMODEL/4);

    // QKV fused GEMM
    bf16_gemm<<<dim3(D3/128, ROWS/128), 256, GEMM_SMEM>>>(
        xh, xl, wqkvTh, wqkvTl, bqkv, QKV, nullptr, nullptr, ROWS, D3, DMODEL, 0);

    dim3 gdash(SEQ/32, BH);
    dash_fused<<<gdash, 256, DASH_SMEM>>>(QKV, D3, Qp, nullptr, nullptr, 1);
    dash_fused<<<gdash, 256, DASH_SMEM>>>(QKV + 1024, D3, Kp, kdiag, kmax, 0);

    kv_ksum_kernel<<<dim3(NCHUNK, BH), 256, KV_SMEM>>>(Kp, QKV + 2048, D3);
    kv_reduce<<<BH, 256>>>();
    attn_fused<<<dim3(SEQ/128, BH), 256>>>(Qp, attn);

    conv_act<<<ROWS*DMODEL/4/256, 256>>>(attn, ah, al, ROWS*DMODEL/4);
    bf16_gemm<<<dim3(DMODEL/128, ROWS/128), 256, GEMM_SMEM>>>(
        ah, al, woTh, woTl, bo, t, nullptr, nullptr, ROWS, DMODEL, DMODEL, 0);
    ln_kernel<<<ROWS, 256>>>(t, x, ln1g, ln1b, x1);
    conv_act<<<ROWS*DMODEL/4/256, 256>>>(x1, x1h, x1l, ROWS*DMODEL/4);

    bf16_gemm<<<dim3(DFF/128, ROWS/128), 256, GEMM_SMEM>>>(
        x1h, x1l, w1Th, w1Tl, b1, nullptr, hh, hl, ROWS, DFF, DMODEL, 1);
    bf16_gemm<<<dim3(DMODEL/128, ROWS/128), 256, GEMM_SMEM>>>(
        hh, hl, w2Th, w2Tl, b2, t, nullptr, nullptr, ROWS, DMODEL, DFF, 0);
    ln_kernel<<<ROWS, 256>>>(t, x1, ln2g, ln2b, out);
}

// round 15
// speedup vs baseline: 1.2142x; 1.2142x over previous
#include <cuda_runtime.h>
#include <math.h>
#include <stdint.h>

#define BB 4
#define SEQ 4096
#define DMODEL 1024
#define NHEAD 16
#define HD 64
#define MF 256
#define DFF 4096
#define ROWS (BB*SEQ)
#define BH (BB*NHEAD)
#define NCHUNK 8
#define D3 (3*DMODEL)

#define DATA_NORM 0.35355339059327373f
#define RATIO     0.0625f
#define KEPS      1e-4f
#define LNEPS     1e-5f

// ---------------- scratch ----------------
__device__ float g_QKV[(size_t)ROWS*D3];
__device__ float g_wqkv[(size_t)DMODEL*D3];
__device__ float g_bqkv[D3];
__device__ float g_Qp[(size_t)BH*SEQ*MF];
__device__ float g_Kp[(size_t)BH*SEQ*MF];
__device__ float g_kdiag[(size_t)BH*SEQ];
__device__ float g_kmax[BH];
__device__ float g_kvpart[(size_t)BH*NCHUNK*MF*HD];
__device__ float g_kspart[(size_t)BH*NCHUNK*MF];
__device__ float g_kv[(size_t)BH*MF*HD];
__device__ float g_ksum[BH*MF];
__device__ float g_attn[(size_t)ROWS*DMODEL];
__device__ float g_x1[(size_t)ROWS*DMODEL];
__device__ float g_hbuf[(size_t)ROWS*DFF];
__device__ float g_t[(size_t)ROWS*DMODEL];
__device__ uint32_t g_projhi[HD*MF];
__device__ uint32_t g_projlo[HD*MF];

// ---------------- helpers ----------------
__device__ __forceinline__ float geluf(float x) {
    return 0.5f * x * (1.f + erff(x * 0.7071067811865476f));
}
__device__ __forceinline__ void atomicMaxF(float* addr, float v) {
    int old = __float_as_int(*addr);
    while (__int_as_float(old) < v) {
        int prev = atomicCAS((int*)addr, old, __float_as_int(v));
        if (prev == old) break;
        old = prev;
    }
}
__device__ __forceinline__ uint32_t f2tf(float f) {
    uint32_t r;
    asm("cvt.rna.tf32.f32 %0, %1;" : "=r"(r) : "f"(f));
    return r;
}
__device__ __forceinline__ float trunctf(float f) {
    return __uint_as_float(__float_as_uint(f) & 0xffffe000u);
}
__device__ __forceinline__ void mma16n8k8(float* c, const uint32_t* a, const uint32_t* b) {
    asm volatile(
        "mma.sync.aligned.m16n8k8.row.col.f32.tf32.tf32.f32 "
        "{%0,%1,%2,%3}, {%4,%5,%6,%7}, {%8,%9}, {%0,%1,%2,%3};"
        : "+f"(c[0]), "+f"(c[1]), "+f"(c[2]), "+f"(c[3])
        : "r"(a[0]), "r"(a[1]), "r"(a[2]), "r"(a[3]), "r"(b[0]), "r"(b[1]));
}
__device__ __forceinline__ void ldsm4(uint32_t* r, uint32_t addr) {
    asm volatile("ldmatrix.sync.aligned.m8n8.x4.shared.b16 {%0,%1,%2,%3}, [%4];"
        : "=r"(r[0]), "=r"(r[1]), "=r"(r[2]), "=r"(r[3]) : "r"(addr));
}
__device__ __forceinline__ void cpasync16(void* s, const void* g) {
    uint32_t saddr = (uint32_t)__cvta_generic_to_shared(s);
    asm volatile("cp.async.cg.shared.global [%0], [%1], 16;" :: "r"(saddr), "l"(g));
}
__device__ __forceinline__ void cpcommit() { asm volatile("cp.async.commit_group;"); }
__device__ __forceinline__ void cpwait0()  { asm volatile("cp.async.wait_group 0;"); }
__device__ __forceinline__ void cpwait1()  { asm volatile("cp.async.wait_group 1;"); }

// ---------------- TF32 GEMM: 128x128xBK32, 3-stage, ldmatrix A-frags (round-10 best) ----------------
#define AS_STRIDE (128*36)
#define BS_STRIDE (32*136)
#define GEMM_SMEM ((3*AS_STRIDE + 3*BS_STRIDE)*4)   // 107,520 B

__global__ __launch_bounds__(256, 2) void tf32_gemm(
    const float* __restrict__ A, const float* __restrict__ B,
    const float* __restrict__ bias, float* __restrict__ C,
    int M, int N, int K, int dogelu)
{
    extern __shared__ float gsm[];
    float* AsBase = gsm;
    float* BsBase = gsm + 3*AS_STRIDE;
    uint32_t as_u32 = (uint32_t)__cvta_generic_to_shared(AsBase);

    int tid = threadIdx.x;
    int lane = tid & 31, wid = tid >> 5;
    int warp_m = wid & 3, warp_n = wid >> 2;
    int row0 = blockIdx.y * 128, col0 = blockIdx.x * 128;

    int ar0 = tid >> 3;
    int ac4 = (tid & 7) << 2;
    int br0 = tid >> 5;
    int bc4 = (tid & 31) << 2;

    const float* Abase = A + (size_t)(row0 + ar0) * K + ac4;
    const float* Bbase = B + (size_t)br0 * N + col0 + bc4;

    uint32_t a_lm_off = (uint32_t)(((warp_m * 32 + (lane & 15)) * 36 + ((lane >> 4) & 1) * 4) * 4);

    float acc[2][8][4];
    #pragma unroll
    for (int i = 0; i < 2; i++)
        #pragma unroll
        for (int j = 0; j < 8; j++)
            #pragma unroll
            for (int l = 0; l < 4; l++) acc[i][j][l] = 0.f;

    int nk = K >> 5;

#define LOAD_STAGE(kt, st)                                                         \
    {                                                                              \
        float* Asm = AsBase + (st) * AS_STRIDE;                                    \
        float* Bsm = BsBase + (st) * BS_STRIDE;                                    \
        const float* Ap = Abase + (kt) * 32;                                       \
        const float* Bp = Bbase + (size_t)(kt) * 32 * N;                           \
        _Pragma("unroll")                                                          \
        for (int i = 0; i < 4; i++)                                                \
            cpasync16(Asm + (ar0 + i*32)*36 + ac4, Ap + (size_t)(i*32) * K);       \
        _Pragma("unroll")                                                          \
        for (int i = 0; i < 4; i++)                                                \
            cpasync16(Bsm + (br0 + i*8)*136 + bc4, Bp + (size_t)(i*8) * N);        \
    }

    LOAD_STAGE(0, 0); cpcommit();
    LOAD_STAGE(1, 1); cpcommit();

    for (int kt = 0; kt < nk; kt++) {
        int cur = kt % 3;
        cpwait1();
        __syncthreads();

        if (kt + 2 < nk) LOAD_STAGE(kt + 2, (kt + 2) % 3);
        cpcommit();

        uint32_t abase = as_u32 + (uint32_t)(cur * AS_STRIDE * 4) + a_lm_off;
        const uint32_t* Bu = (const uint32_t*)(BsBase + cur * BS_STRIDE);

        #pragma unroll
        for (int ks = 0; ks < 4; ks++) {
            int k0 = ks * 8;
            uint32_t a[2][4];
            ldsm4(a[0], abase + (uint32_t)(k0 * 4));
            ldsm4(a[1], abase + (uint32_t)((16*36 + k0) * 4));
            uint32_t b[8][2];
            #pragma unroll
            for (int bn = 0; bn < 8; bn++) {
                int n = warp_n * 64 + bn * 8 + (lane >> 2);
                int kk = k0 + (lane & 3);
                b[bn][0] = Bu[kk*136 + n];
                b[bn][1] = Bu[(kk+4)*136 + n];
            }
            #pragma unroll
            for (int am = 0; am < 2; am++)
                #pragma unroll
                for (int bn = 0; bn < 8; bn++)
                    mma16n8k8(acc[am][bn], a[am], b[bn]);
        }
    }
#undef LOAD_STAGE

    #pragma unroll
    for (int am = 0; am < 2; am++) {
        int r = row0 + warp_m * 32 + am * 16 + (lane >> 2);
        #pragma unroll
        for (int bn = 0; bn < 8; bn++) {
            int c = col0 + warp_n * 64 + bn * 8 + (lane & 3) * 2;
            float2 bv = *(const float2*)(bias + c);
            float v0 = acc[am][bn][0] + bv.x;
            float v1 = acc[am][bn][1] + bv.y;
            float v2 = acc[am][bn][2] + bv.x;
            float v3 = acc[am][bn][3] + bv.y;
            if (dogelu) { v0 = geluf(v0); v1 = geluf(v1); v2 = geluf(v2); v3 = geluf(v3); }
            float2 w0 = {v0, v1}, w1 = {v2, v3};
            *(float2*)(C + (size_t)r * N + c)       = w0;
            *(float2*)(C + (size_t)(r + 8) * N + c) = w1;
        }
    }
}

// ---------------- prep: pack wq|wk|wv and biases ----------------
__global__ __launch_bounds__(256) void pack_qkv(
    const float* __restrict__ wq, const float* __restrict__ wk, const float* __restrict__ wv,
    const float* __restrict__ bq, const float* __restrict__ bk, const float* __restrict__ bv)
{
    int idx = blockIdx.x * 256 + threadIdx.x;
    int k = idx >> 10, n = idx & 1023;
    g_wqkv[(size_t)k * D3 + n]          = wq[idx];
    g_wqkv[(size_t)k * D3 + 1024 + n]   = wk[idx];
    g_wqkv[(size_t)k * D3 + 2048 + n]   = wv[idx];
    if (idx < DMODEL) {
        g_bqkv[idx] = bq[idx];
        g_bqkv[1024 + idx] = bk[idx];
        g_bqkv[2048 + idx] = bv[idx];
    }
}

// ---------------- proj prep ----------------
__global__ void prep_proj(const float* __restrict__ proj) {
    int i = blockIdx.x * 256 + threadIdx.x;
    if (i < HD * MF) {
        int d = i >> 8, m = i & 255;
        float v = proj[m * HD + d];
        uint32_t h = f2tf(v);
        g_projhi[i] = h;
        g_projlo[i] = f2tf(v - __uint_as_float(h));
    }
}
__global__ void kmax_init() { if (threadIdx.x < BH) g_kmax[threadIdx.x] = -3.4e38f; }

// ---------------- fused dash: proj loaded once, 4x32-row sub-tiles per block ----------------
#define DPH_OFF 0
#define DPL_OFF 67584
#define DAH_OFF 135168
#define DAL_OFF 143872
#define DSD_OFF 152576
#define DSM_OFF 152704
#define DWM_OFF 152832
#define DASH_SMEM 153856

extern "C" __global__ __launch_bounds__(256) void dash_fused(
    const float* __restrict__ data, int ldd, float* __restrict__ outp,
    float* __restrict__ kdiag, float* __restrict__ kmaxbuf, int isquery)
{
    extern __shared__ unsigned char dsm[];
    uint32_t (*Ph)[264] = (uint32_t(*)[264])(dsm + DPH_OFF);
    uint32_t (*Pl)[264] = (uint32_t(*)[264])(dsm + DPL_OFF);
    uint32_t (*Ah)[68]  = (uint32_t(*)[68])(dsm + DAH_OFF);
    uint32_t (*Al)[68]  = (uint32_t(*)[68])(dsm + DAL_OFF);
    float* sdiag = (float*)(dsm + DSD_OFF);
    float* smax  = (float*)(dsm + DSM_OFF);
    float* wmax  = (float*)(dsm + DWM_OFF);

    int bh = blockIdx.y, b = bh >> 4, h = bh & 15;
    int tid = threadIdx.x, lane = tid & 31, wid = tid >> 5;

    // proj hi/lo -> smem ONCE per block
    #pragma unroll
    for (int i = 0; i < 16; i++) {
        int cid = i * 256 + tid;
        int r = cid >> 6, c = (cid & 63) * 4;
        cpasync16(&Ph[r][c], g_projhi + r * 256 + c);
        cpasync16(&Pl[r][c], g_projlo + r * 256 + c);
    }
    cpcommit();
    cpwait0();
    __syncthreads();

    for (int st = 0; st < 4; st++) {
        int n0 = blockIdx.x * 128 + st * 32;

        // A tile: 32 rows x 64, sumsq + tf32 hi/lo split
        {
            int r = tid >> 3, c0 = (tid & 7) * 8;
            const float* src = data + ((size_t)(b * SEQ + n0 + r)) * ldd + h * HD + c0;
            float4 v0 = *(const float4*)src;
            float4 v1 = *(const float4*)(src + 4);
            float ss = v0.x*v0.x + v0.y*v0.y + v0.z*v0.z + v0.w*v0.w
                     + v1.x*v1.x + v1.y*v1.y + v1.z*v1.z + v1.w*v1.w;
            ss += __shfl_xor_sync(~0u, ss, 1);
            ss += __shfl_xor_sync(~0u, ss, 2);
            ss += __shfl_xor_sync(~0u, ss, 4);
            if ((tid & 7) == 0) sdiag[r] = 0.0625f * ss;
            float a[8] = {v0.x,v0.y,v0.z,v0.w,v1.x,v1.y,v1.z,v1.w};
            #pragma unroll
            for (int j = 0; j < 8; j++) {
                float av = DATA_NORM * a[j];
                uint32_t hi = f2tf(av);
                Ah[r][c0+j] = hi;
                Al[r][c0+j] = f2tf(av - __uint_as_float(hi));
            }
        }
        __syncthreads();

        float acc[2][4][4];
        #pragma unroll
        for (int i = 0; i < 2; i++)
            #pragma unroll
            for (int j = 0; j < 4; j++)
                #pragma unroll
                for (int l = 0; l < 4; l++) acc[i][j][l] = 0.f;

        int ncol = wid * 32;
        #pragma unroll
        for (int k0 = 0; k0 < 64; k0 += 8) {
            uint32_t ah[2][4], al[2][4];
            #pragma unroll
            for (int mt = 0; mt < 2; mt++) {
                int r = mt * 16 + (lane >> 2), c = k0 + (lane & 3);
                ah[mt][0] = Ah[r][c];    ah[mt][1] = Ah[r+8][c];
                ah[mt][2] = Ah[r][c+4];  ah[mt][3] = Ah[r+8][c+4];
                al[mt][0] = Al[r][c];    al[mt][1] = Al[r+8][c];
                al[mt][2] = Al[r][c+4];  al[mt][3] = Al[r+8][c+4];
            }
            uint32_t bhf[4][2], blf[4][2];
            #pragma unroll
            for (int nt = 0; nt < 4; nt++) {
                int n = ncol + nt * 8 + (lane >> 2), kk = k0 + (lane & 3);
                bhf[nt][0] = Ph[kk][n];   bhf[nt][1] = Ph[kk+4][n];
                blf[nt][0] = Pl[kk][n];   blf[nt][1] = Pl[kk+4][n];
            }
            #pragma unroll
            for (int mt = 0; mt < 2; mt++)
                #pragma unroll
                for (int nt = 0; nt < 4; nt++) {
                    mma16n8k8(acc[mt][nt], ah[mt], bhf[nt]);
                    mma16n8k8(acc[mt][nt], ah[mt], blf[nt]);
                    mma16n8k8(acc[mt][nt], al[mt], bhf[nt]);
                }
        }

        #pragma unroll
        for (int mt = 0; mt < 2; mt++) {
            float m0 = -3.4e38f, m1 = -3.4e38f;
            #pragma unroll
            for (int nt = 0; nt < 4; nt++) {
                m0 = fmaxf(m0, fmaxf(acc[mt][nt][0], acc[mt][nt][1]));
                m1 = fmaxf(m1, fmaxf(acc[mt][nt][2], acc[mt][nt][3]));
            }
            m0 = fmaxf(m0, __shfl_xor_sync(~0u, m0, 1));
            m0 = fmaxf(m0, __shfl_xor_sync(~0u, m0, 2));
            m1 = fmaxf(m1, __shfl_xor_sync(~0u, m1, 1));
            m1 = fmaxf(m1, __shfl_xor_sync(~0u, m1, 2));
            if ((lane & 3) == 0) {
                wmax[wid * 32 + mt * 16 + (lane >> 2)]     = m0;
                wmax[wid * 32 + mt * 16 + 8 + (lane >> 2)] = m1;
            }
        }
        __syncthreads();
        if (tid < 32) {
            float mx = wmax[tid];
            #pragma unroll
            for (int w = 1; w < 8; w++) mx = fmaxf(mx, wmax[w * 32 + tid]);
            smax[tid] = mx;
        }
        __syncthreads();
        if (!isquery) {
            if (tid < 32) kdiag[(size_t)bh * SEQ + n0 + tid] = sdiag[tid];
            if (tid == 0) {
                float bm = smax[0];
                #pragma unroll
                for (int i = 1; i < 32; i++) bm = fmaxf(bm, smax[i]);
                atomicMaxF(&kmaxbuf[bh], bm);
            }
        }

        #pragma unroll
        for (int mt = 0; mt < 2; mt++) {
            int r = mt * 16 + (lane >> 2);
            #pragma unroll
            for (int nt = 0; nt < 4; nt++) {
                int c = ncol + nt * 8 + (lane & 3) * 2;
                float v0 = acc[mt][nt][0], v1 = acc[mt][nt][1];
                float v2 = acc[mt][nt][2], v3 = acc[mt][nt][3];
                if (isquery) {
                    float s0 = sdiag[r] + smax[r];
                    float s1 = sdiag[r+8] + smax[r+8];
                    v0 = RATIO * (__expf(v0 - s0) + KEPS);
                    v1 = RATIO * (__expf(v1 - s0) + KEPS);
                    v2 = RATIO * (__expf(v2 - s1) + KEPS);
                    v3 = RATIO * (__expf(v3 - s1) + KEPS);
                }
                float2 w0 = {v0, v1}, w1 = {v2, v3};
                *(float2*)(outp + ((size_t)bh * SEQ + n0 + r) * MF + c)     = w0;
                *(float2*)(outp + ((size_t)bh * SEQ + n0 + r + 8) * MF + c) = w1;
            }
        }
        __syncthreads();
    }
}

// ---------------- kv + ksum ----------------
#define KAS_OFF 0
#define KVS_OFF 40960
#define KSR_OFF 50176
#define KV_SMEM 54272

extern "C" __global__ __launch_bounds__(256) void kv_ksum_kernel(
    const float* __restrict__ Kraw, const float* __restrict__ V, int ldv)
{
    extern __shared__ unsigned char ksm[];
    float (*As)[256][20] = (float(*)[256][20])(ksm + KAS_OFF);
    float (*Vs)[16][72]  = (float(*)[16][72])(ksm + KVS_OFF);
    float (*sred)[256]   = (float(*)[256])(ksm + KSR_OFF);

    int bh = blockIdx.y, chunk = blockIdx.x;
    int b = bh >> 4, h = bh & 15;
    int tid = threadIdx.x, lane = tid & 31, wid = tid >> 5;
    int wm = wid & 3, wn = wid >> 2;

    float kmax = g_kmax[bh];
    const float* Kb  = Kraw + ((size_t)bh * SEQ + chunk * 512) * MF;
    const float* Vb  = V + ((size_t)(b * SEQ + chunk * 512)) * ldv + h * HD;
    const float* dgb = g_kdiag + (size_t)bh * SEQ + chunk * 512;

    int mcol = tid & 63;
    int nr   = tid >> 6;
    float ks[4] = {0.f, 0.f, 0.f, 0.f};

    float acc[4][4][4];
    #pragma unroll
    for (int i = 0; i < 4; i++)
        #pragma unroll
        for (int j = 0; j < 4; j++)
            #pragma unroll
            for (int l = 0; l < 4; l++) acc[i][j][l] = 0.f;

#define LOAD_TILE(nt, buf)                                                        \
    {                                                                             \
        _Pragma("unroll")                                                         \
        for (int p = 0; p < 4; p++) {                                             \
            int nl = p * 4 + nr;                                                  \
            int ng = (nt) * 16 + nl;                                              \
            float dg = dgb[ng] + kmax;                                            \
            const float* kr = Kb + (size_t)ng * MF + mcol;                        \
            float r0 = kr[0], r1 = kr[64], r2 = kr[128], r3 = kr[192];            \
            float e0 = trunctf(RATIO * (__expf(r0 - dg) + KEPS));                 \
            float e1 = trunctf(RATIO * (__expf(r1 - dg) + KEPS));                 \
            float e2 = trunctf(RATIO * (__expf(r2 - dg) + KEPS));                 \
            float e3 = trunctf(RATIO * (__expf(r3 - dg) + KEPS));                 \
            ks[0] += e0; ks[1] += e1; ks[2] += e2; ks[3] += e3;                   \
            As[buf][mcol][nl] = e0;   As[buf][mcol+64][nl] = e1;                  \
            As[buf][mcol+128][nl] = e2; As[buf][mcol+192][nl] = e3;               \
        }                                                                         \
        cpasync16(&Vs[buf][tid >> 4][(tid & 15) * 4],                             \
                  Vb + (size_t)((nt) * 16 + (tid >> 4)) * ldv + (tid & 15) * 4);  \
        cpcommit();                                                               \
    }

    LOAD_TILE(0, 0);

    for (int nt = 0; nt < 32; nt++) {
        int buf = nt & 1;
        cpwait0();
        __syncthreads();
        if (nt + 1 < 32) LOAD_TILE(nt + 1, buf ^ 1);

        const uint32_t (*Au)[20] = (const uint32_t(*)[20])As[buf];
        const uint32_t (*Vu)[72] = (const uint32_t(*)[72])Vs[buf];

        #pragma unroll
        for (int ks2 = 0; ks2 < 2; ks2++) {
            int k0 = ks2 * 8;
            uint32_t a[4][4];
            #pragma unroll
            for (int mt = 0; mt < 4; mt++) {
                int r = wm * 64 + mt * 16 + (lane >> 2), c = k0 + (lane & 3);
                a[mt][0] = Au[r][c];
                a[mt][1] = Au[r+8][c];
                a[mt][2] = Au[r][c+4];
                a[mt][3] = Au[r+8][c+4];
            }
            uint32_t bb[4][2];
            #pragma unroll
            for (int dt = 0; dt < 4; dt++) {
                int n = wn * 32 + dt * 8 + (lane >> 2), kk = k0 + (lane & 3);
                bb[dt][0] = Vu[kk][n];
                bb[dt][1] = Vu[kk+4][n];
            }
            #pragma unroll
            for (int mt = 0; mt < 4; mt++)
                #pragma unroll
                for (int dt = 0; dt < 4; dt++)
                    mma16n8k8(acc[mt][dt], a[mt], bb[dt]);
        }
    }
#undef LOAD_TILE

    float* kvp = g_kvpart + ((size_t)(bh * NCHUNK + chunk)) * MF * HD;
    #pragma unroll
    for (int mt = 0; mt < 4; mt++) {
        int m = wm * 64 + mt * 16 + (lane >> 2);
        #pragma unroll
        for (int dt = 0; dt < 4; dt++) {
            int d = wn * 32 + dt * 8 + (lane & 3) * 2;
            float2 w0 = {acc[mt][dt][0], acc[mt][dt][1]};
            float2 w1 = {acc[mt][dt][2], acc[mt][dt][3]};
            *(float2*)(kvp + (size_t)m * HD + d)       = w0;
            *(float2*)(kvp + (size_t)(m + 8) * HD + d) = w1;
        }
    }
    __syncthreads();
    sred[nr][mcol]       = ks[0];
    sred[nr][mcol + 64]  = ks[1];
    sred[nr][mcol + 128] = ks[2];
    sred[nr][mcol + 192] = ks[3];
    __syncthreads();
    float s = sred[0][tid & 255] + sred[1][tid & 255] + sred[2][tid & 255] + sred[3][tid & 255];
    g_kspart[(size_t)(bh * NCHUNK + chunk) * MF + tid] = s;
}

// ---------------- reduce partials ----------------
__global__ __launch_bounds__(256) void kv_reduce() {
    int bh = blockIdx.x, tid = threadIdx.x;
    for (int i = tid; i < MF * HD; i += 256) {
        float s = 0.f;
        #pragma unroll
        for (int c = 0; c < NCHUNK; c++)
            s += g_kvpart[((size_t)(bh * NCHUNK + c)) * MF * HD + i];
        g_kv[(size_t)bh * MF * HD + i] = s;
    }
    float s = 0.f;
    #pragma unroll
    for (int c = 0; c < NCHUNK; c++)
        s += g_kspart[(size_t)(bh * NCHUNK + c) * MF + tid];
    g_ksum[bh * MF + tid] = s;
}

// ---------------- attn + denom fused ----------------
__global__ __launch_bounds__(256) void attn_fused(
    const float* __restrict__ Qp, float* __restrict__ out)
{
    __shared__ float Qs[2][128][20];
    __shared__ float Bs[2][16][72];
    __shared__ float sk[256];
    __shared__ float sdn[128];

    int bh = blockIdx.y, b = bh >> 4, h = bh & 15;
    int n0 = blockIdx.x * 128;
    int tid = threadIdx.x, lane = tid & 31, wid = tid >> 5;
    int wm = wid & 3, wn = wid >> 2;

    sk[tid] = g_ksum[bh * MF + tid];

    const float* Qb = Qp + ((size_t)bh * SEQ + n0) * MF;
    const float* Vb = g_kv + (size_t)bh * MF * HD;

#define LOADQ(kt, buf)                                                        \
    {                                                                         \
        _Pragma("unroll")                                                     \
        for (int i = 0; i < 2; i++) {                                         \
            int cid = i * 256 + tid;                                          \
            int r = cid >> 2, c = (cid & 3) * 4;                              \
            cpasync16(&Qs[buf][r][c], Qb + (size_t)r * MF + (kt) * 16 + c);   \
        }                                                                     \
        cpasync16(&Bs[buf][tid >> 4][(tid & 15) * 4],                         \
                  Vb + (size_t)((kt) * 16 + (tid >> 4)) * HD + (tid & 15) * 4); \
        cpcommit();                                                           \
    }

    LOADQ(0, 0);

    float acc[2][4][4];
    #pragma unroll
    for (int i = 0; i < 2; i++)
        #pragma unroll
        for (int j = 0; j < 4; j++)
            #pragma unroll
            for (int l = 0; l < 4; l++) acc[i][j][l] = 0.f;
    float dn = 0.f;

    for (int kt = 0; kt < 16; kt++) {
        int buf = kt & 1;
        cpwait0();
        __syncthreads();
        if (kt + 1 < 16) LOADQ(kt + 1, buf ^ 1);

        if (tid < 128) {
            #pragma unroll
            for (int j = 0; j < 16; j++) dn += trunctf(Qs[buf][tid][j]) * sk[kt * 16 + j];
        }

        const uint32_t (*Qu)[20] = (const uint32_t(*)[20])Qs[buf];
        const uint32_t (*Bu)[72] = (const uint32_t(*)[72])Bs[buf];

        #pragma unroll
        for (int ks2 = 0; ks2 < 2; ks2++) {
            int k0 = ks2 * 8;
            uint32_t a[2][4];
            #pragma unroll
            for (int mt = 0; mt < 2; mt++) {
                int r = wm * 32 + mt * 16 + (lane >> 2), c = k0 + (lane & 3);
                a[mt][0] = Qu[r][c];
                a[mt][1] = Qu[r+8][c];
                a[mt][2] = Qu[r][c+4];
                a[mt][3] = Qu[r+8][c+4];
            }
            uint32_t bb[4][2];
            #pragma unroll
            for (int dt = 0; dt < 4; dt++) {
                int n = wn * 32 + dt * 8 + (lane >> 2), kk = k0 + (lane & 3);
                bb[dt][0] = Bu[kk][n];
                bb[dt][1] = Bu[kk+4][n];
            }
            #pragma unroll
            for (int mt = 0; mt < 2; mt++)
                #pragma unroll
                for (int dt = 0; dt < 4; dt++)
                    mma16n8k8(acc[mt][dt], a[mt], bb[dt]);
        }
    }
#undef LOADQ

    if (tid < 128) sdn[tid] = dn;
    __syncthreads();

    #pragma unroll
    for (int mt = 0; mt < 2; mt++) {
        int r = wm * 32 + mt * 16 + (lane >> 2);
        float i0 = 1.f / sdn[r];
        float i1 = 1.f / sdn[r + 8];
        #pragma unroll
        for (int dt = 0; dt < 4; dt++) {
            int c = wn * 32 + dt * 8 + (lane & 3) * 2;
            float2 w0 = {acc[mt][dt][0] * i0, acc[mt][dt][1] * i0};
            float2 w1 = {acc[mt][dt][2] * i1, acc[mt][dt][3] * i1};
            *(float2*)(out + ((size_t)(b * SEQ + n0 + r)) * DMODEL + h * HD + c)     = w0;
            *(float2*)(out + ((size_t)(b * SEQ + n0 + r + 8)) * DMODEL + h * HD + c) = w1;
        }
    }
}

// ---------------- fused residual + LayerNorm ----------------
__global__ __launch_bounds__(256) void ln_kernel(
    const float* __restrict__ a, const float* __restrict__ res,
    const float* __restrict__ gam, const float* __restrict__ bet, float* __restrict__ out)
{
    __shared__ float red[8];
    int row = blockIdx.x, tid = threadIdx.x;
    int lane = tid & 31, w = tid >> 5;
    size_t base = (size_t)row * DMODEL + tid * 4;
    float4 v = *(const float4*)(a + base);
    float4 r = *(const float4*)(res + base);
    v.x += r.x; v.y += r.y; v.z += r.z; v.w += r.w;

    float s = v.x + v.y + v.z + v.w;
    #pragma unroll
    for (int o = 16; o; o >>= 1) s += __shfl_xor_sync(0xffffffffu, s, o);
    if (lane == 0) red[w] = s;
    __syncthreads();
    float t = (tid < 8) ? red[tid] : 0.f;
    if (w == 0) {
        #pragma unroll
        for (int o = 4; o; o >>= 1) t += __shfl_xor_sync(0xffffffffu, t, o);
        if (lane == 0) red[0] = t;
    }
    __syncthreads();
    float mean = red[0] * (1.f / DMODEL);
    __syncthreads();

    float d0 = v.x - mean, d1 = v.y - mean, d2 = v.z - mean, d3 = v.w - mean;
    float s2 = d0*d0 + d1*d1 + d2*d2 + d3*d3;
    #pragma unroll
    for (int o = 16; o; o >>= 1) s2 += __shfl_xor_sync(0xffffffffu, s2, o);
    if (lane == 0) red[w] = s2;
    __syncthreads();
    float t2 = (tid < 8) ? red[tid] : 0.f;
    if (w == 0) {
        #pragma unroll
        for (int o = 4; o; o >>= 1) t2 += __shfl_xor_sync(0xffffffffu, t2, o);
        if (lane == 0) red[0] = t2;
    }
    __syncthreads();
    float var = red[0] * (1.f / DMODEL);
    float inv = rsqrtf(var + LNEPS);

    float4 g4 = *(const float4*)(gam + tid * 4);
    float4 b4 = *(const float4*)(bet + tid * 4);
    float4 o4;
    o4.x = d0 * inv * g4.x + b4.x;
    o4.y = d1 * inv * g4.y + b4.y;
    o4.z = d2 * inv * g4.z + b4.z;
    o4.w = d3 * inv * g4.w + b4.w;
    *(float4*)(out + base) = o4;
}

// ---------------- launch ----------------
extern "C" void kernel_launch(void* const* d_in, const int* in_sizes, int n_in,
                              void* d_out, int out_size)
{
    const float* x  = (const float*)d_in[0];
    const float* wq = (const float*)d_in[1];  const float* bq = (const float*)d_in[2];
    const float* wk = (const float*)d_in[3];  const float* bk = (const float*)d_in[4];
    const float* wv = (const float*)d_in[5];  const float* bv = (const float*)d_in[6];
    const float* wo = (const float*)d_in[7];  const float* bo = (const float*)d_in[8];
    const float* proj = (const float*)d_in[9];
    const float* w1 = (const float*)d_in[10]; const float* b1 = (const float*)d_in[11];
    const float* w2 = (const float*)d_in[12]; const float* b2 = (const float*)d_in[13];
    const float* ln1g = (const float*)d_in[14]; const float* ln1b = (const float*)d_in[15];
    const float* ln2g = (const float*)d_in[16]; const float* ln2b = (const float*)d_in[17];
    float* out = (float*)d_out;

    static int attr_done = 0;
    if (!attr_done) {
        cudaFuncSetAttribute(tf32_gemm, cudaFuncAttributeMaxDynamicSharedMemorySize, GEMM_SMEM);
        cudaFuncSetAttribute(dash_fused, cudaFuncAttributeMaxDynamicSharedMemorySize, DASH_SMEM);
        cudaFuncSetAttribute(kv_ksum_kernel, cudaFuncAttributeMaxDynamicSharedMemorySize, KV_SMEM);
        attr_done = 1;
    }

    float *QKV, *wqkv, *bqkv, *Qp, *Kp, *kdiag, *kmax, *attn, *x1, *h, *t;
    cudaGetSymbolAddress((void**)&QKV, g_QKV);
    cudaGetSymbolAddress((void**)&wqkv, g_wqkv);
    cudaGetSymbolAddress((void**)&bqkv, g_bqkv);
    cudaGetSymbolAddress((void**)&Qp, g_Qp);
    cudaGetSymbolAddress((void**)&Kp, g_Kp);
    cudaGetSymbolAddress((void**)&kdiag, g_kdiag);
    cudaGetSymbolAddress((void**)&kmax, g_kmax);
    cudaGetSymbolAddress((void**)&attn, g_attn);
    cudaGetSymbolAddress((void**)&x1, g_x1);
    cudaGetSymbolAddress((void**)&h,  g_hbuf);
    cudaGetSymbolAddress((void**)&t,  g_t);

    prep_proj<<<64, 256>>>(proj);
    kmax_init<<<1, 64>>>();
    pack_qkv<<<DMODEL*DMODEL/256, 256>>>(wq, wk, wv, bq, bk, bv);

    tf32_gemm<<<dim3(D3/128, ROWS/128), 256, GEMM_SMEM>>>(x, wqkv, bqkv, QKV, ROWS, D3, DMODEL, 0);

    dim3 gdash(SEQ/128, BH);
    dash_fused<<<gdash, 256, DASH_SMEM>>>(QKV, D3, Qp, nullptr, nullptr, 1);
    dash_fused<<<gdash, 256, DASH_SMEM>>>(QKV + 1024, D3, Kp, kdiag, kmax, 0);

    kv_ksum_kernel<<<dim3(NCHUNK, BH), 256, KV_SMEM>>>(Kp, QKV + 2048, D3);
    kv_reduce<<<BH, 256>>>();
    attn_fused<<<dim3(SEQ/128, BH), 256>>>(Qp, attn);

    dim3 gqkv(DMODEL/128, ROWS/128);
    tf32_gemm<<<gqkv, 256, GEMM_SMEM>>>(attn, wo, bo, t, ROWS, DMODEL, DMODEL, 0);
    ln_kernel<<<ROWS, 256>>>(t, x, ln1g, ln1b, x1);

    tf32_gemm<<<dim3(DFF/128, ROWS/128), 256, GEMM_SMEM>>>(x1, w1, b1, h, ROWS, DFF, DMODEL, 1);
    tf32_gemm<<<gqkv, 256, GEMM_SMEM>>>(h, w2, b2, t, ROWS, DMODEL, DFF, 0);
    ln_kernel<<<ROWS, 256>>>(t, x1, ln2g, ln2b, out);
}

// round 16
// speedup vs baseline: 1.9193x; 1.5807x over previous
#include <cuda_runtime.h>
#include <cuda_fp16.h>
#include <math.h>
#include <stdint.h>

#define BB 4
#define SEQ 4096
#define DMODEL 1024
#define NHEAD 16
#define HD 64
#define MF 256
#define DFF 4096
#define ROWS (BB*SEQ)
#define BH (BB*NHEAD)
#define NCHUNK 8
#define D3 (3*DMODEL)

#define DATA_NORM 0.35355339059327373f
#define RATIO     0.0625f
#define KEPS      1e-4f
#define LNEPS     1e-5f

// ---------------- scratch ----------------
__device__ float g_QKV[(size_t)ROWS*D3];
__device__ float g_bqkv[D3];
__device__ float g_Qp[(size_t)BH*SEQ*MF];
__device__ float g_Kp[(size_t)BH*SEQ*MF];
__device__ float g_kdiag[(size_t)BH*SEQ];
__device__ float g_kmax[BH];
__device__ float g_kvpart[(size_t)BH*NCHUNK*MF*HD];
__device__ float g_kspart[(size_t)BH*NCHUNK*MF];
__device__ float g_kv[(size_t)BH*MF*HD];
__device__ float g_ksum[BH*MF];
__device__ float g_attn[(size_t)ROWS*DMODEL];
__device__ float g_x1[(size_t)ROWS*DMODEL];
__device__ float g_t[(size_t)ROWS*DMODEL];
__device__ uint32_t g_projhi[HD*MF];
__device__ uint32_t g_projlo[HD*MF];

// fp16 operands
__device__ __half g_x16[(size_t)ROWS*DMODEL];
__device__ __half g_a16[(size_t)ROWS*DMODEL];
__device__ __half g_x116[(size_t)ROWS*DMODEL];
__device__ __half g_h16[(size_t)ROWS*DFF];
__device__ __half g_wqkvT16[(size_t)D3*DMODEL];
__device__ __half g_woT16[DMODEL*DMODEL];
__device__ __half g_w1T16[(size_t)DFF*DMODEL];
__device__ __half g_w2T16[(size_t)DMODEL*DFF];

// ---------------- helpers ----------------
__device__ __forceinline__ float geluf(float x) {
    return 0.5f * x * (1.f + erff(x * 0.7071067811865476f));
}
__device__ __forceinline__ void atomicMaxF(float* addr, float v) {
    int old = __float_as_int(*addr);
    while (__int_as_float(old) < v) {
        int prev = atomicCAS((int*)addr, old, __float_as_int(v));
        if (prev == old) break;
        old = prev;
    }
}
__device__ __forceinline__ uint32_t f2tf(float f) {
    uint32_t r;
    asm("cvt.rna.tf32.f32 %0, %1;" : "=r"(r) : "f"(f));
    return r;
}
__device__ __forceinline__ float trunctf(float f) {
    return __uint_as_float(__float_as_uint(f) & 0xffffe000u);
}
__device__ __forceinline__ void mma16n8k8(float* c, const uint32_t* a, const uint32_t* b) {
    asm volatile(
        "mma.sync.aligned.m16n8k8.row.col.f32.tf32.tf32.f32 "
        "{%0,%1,%2,%3}, {%4,%5,%6,%7}, {%8,%9}, {%0,%1,%2,%3};"
        : "+f"(c[0]), "+f"(c[1]), "+f"(c[2]), "+f"(c[3])
        : "r"(a[0]), "r"(a[1]), "r"(a[2]), "r"(a[3]), "r"(b[0]), "r"(b[1]));
}
__device__ __forceinline__ void mma_f16(float* c, const uint32_t* a, const uint32_t* b) {
    asm volatile(
        "mma.sync.aligned.m16n8k16.row.col.f32.f16.f16.f32 "
        "{%0,%1,%2,%3}, {%4,%5,%6,%7}, {%8,%9}, {%0,%1,%2,%3};"
        : "+f"(c[0]), "+f"(c[1]), "+f"(c[2]), "+f"(c[3])
        : "r"(a[0]), "r"(a[1]), "r"(a[2]), "r"(a[3]), "r"(b[0]), "r"(b[1]));
}
__device__ __forceinline__ void ldsm4(uint32_t* r, uint32_t addr) {
    asm volatile("ldmatrix.sync.aligned.m8n8.x4.shared.b16 {%0,%1,%2,%3}, [%4];"
        : "=r"(r[0]), "=r"(r[1]), "=r"(r[2]), "=r"(r[3]) : "r"(addr));
}
__device__ __forceinline__ void cpasync16(void* s, const void* g) {
    uint32_t saddr = (uint32_t)__cvta_generic_to_shared(s);
    asm volatile("cp.async.cg.shared.global [%0], [%1], 16;" :: "r"(saddr), "l"(g));
}
__device__ __forceinline__ void cpasync16a(uint32_t saddr, const void* g) {
    asm volatile("cp.async.cg.shared.global [%0], [%1], 16;" :: "r"(saddr), "l"(g));
}
__device__ __forceinline__ void cpcommit() { asm volatile("cp.async.commit_group;"); }
__device__ __forceinline__ void cpwait0()  { asm volatile("cp.async.wait_group 0;"); }
__device__ __forceinline__ void cpwait1()  { asm volatile("cp.async.wait_group 1;"); }

// ---------------- conversions ----------------
__global__ __launch_bounds__(256) void conv_act_h(
    const float* __restrict__ src, __half* __restrict__ dst, int n4)
{
    int i = blockIdx.x * 256 + threadIdx.x;
    if (i >= n4) return;
    float4 v = ((const float4*)src)[i];
    __half2 p0 = __floats2half2_rn(v.x, v.y);
    __half2 p1 = __floats2half2_rn(v.z, v.w);
    uint2 u = {*(uint32_t*)&p0, *(uint32_t*)&p1};
    ((uint2*)dst)[i] = u;
}
// weight [K,N] fp32 -> [N,K] fp16 (transposed)
__global__ __launch_bounds__(256) void wt_conv_h(
    const float* __restrict__ src, __half* __restrict__ dst, int K, int N)
{
    __shared__ float tile[32][33];
    int n0 = blockIdx.x * 32, k0 = blockIdx.y * 32;
    int tid = threadIdx.x;
    int c = tid & 31, r0 = (tid >> 5) * 4;
    #pragma unroll
    for (int rr = 0; rr < 4; rr++)
        tile[r0 + rr][c] = src[(size_t)(k0 + r0 + rr) * N + n0 + c];
    __syncthreads();
    int j = tid & 31, i0 = (tid >> 5) * 4;
    #pragma unroll
    for (int ii = 0; ii < 4; ii++)
        dst[(size_t)(n0 + i0 + ii) * K + k0 + j] = __float2half_rn(tile[j][i0 + ii]);
}
__global__ void pack_bias(const float* bq, const float* bk, const float* bv) {
    int i = blockIdx.x * 256 + threadIdx.x;
    if (i < DMODEL) {
        g_bqkv[i] = bq[i];
        g_bqkv[1024 + i] = bk[i];
        g_bqkv[2048 + i] = bv[i];
    }
}

// ---------------- fp16 GEMM: 128x128xBK32, 3-stage, swizzled ldmatrix (round-14 validated) ----------------
#define GS_A 0
#define GS_B 8192
#define GS_STAGE 16384
#define GEMM_SMEM (3*GS_STAGE)   // 49152 B

__global__ __launch_bounds__(256, 2) void fp16_gemm(
    const __half* __restrict__ A_, const __half* __restrict__ B_,
    const float* __restrict__ bias, float* __restrict__ Cf,
    __half* __restrict__ Ch, int M, int N, int K, int mode)
{
    extern __shared__ char gsm[];
    uint32_t sb = (uint32_t)__cvta_generic_to_shared(gsm);

    int tid = threadIdx.x, lane = tid & 31, wid = tid >> 5;
    int warp_m = wid & 3, warp_n = wid >> 2;
    int row0 = blockIdx.y * 128, col0 = blockIdx.x * 128;

    int lrow = tid >> 2, lc = tid & 3;

    int aR = warp_m * 32 + (lane & 15);
    int aKh = lane >> 4;
    int bN  = warp_n * 64 + (lane & 7) + ((lane >> 4) & 1) * 8;
    int bKh = (lane >> 3) & 1;

    float acc[2][8][4];
    #pragma unroll
    for (int i = 0; i < 2; i++)
        #pragma unroll
        for (int j = 0; j < 8; j++)
            #pragma unroll
            for (int l = 0; l < 4; l++) acc[i][j][l] = 0.f;

    int nk = K >> 5;

#define LOAD_STAGE(kt, st)                                                            \
    {                                                                                 \
        uint32_t stb = sb + (st) * GS_STAGE;                                          \
        int kc = (kt) * 32;                                                           \
        _Pragma("unroll")                                                             \
        for (int i = 0; i < 2; i++) {                                                 \
            int row = lrow + i * 64;                                                  \
            uint32_t so = (uint32_t)(row * 64 + ((lc ^ ((row >> 1) & 3)) << 4));      \
            cpasync16a(stb + GS_A + so, A_ + (size_t)(row0 + row) * K + kc + lc * 8); \
            cpasync16a(stb + GS_B + so, B_ + (size_t)(col0 + row) * K + kc + lc * 8); \
        }                                                                             \
    }

    LOAD_STAGE(0, 0); cpcommit();
    LOAD_STAGE(1, 1); cpcommit();

    for (int kt = 0; kt < nk; kt++) {
        int cur = kt % 3;
        cpwait1();
        __syncthreads();

        if (kt + 2 < nk) LOAD_STAGE(kt + 2, (kt + 2) % 3);
        cpcommit();

        uint32_t stb = sb + cur * GS_STAGE;

        #pragma unroll
        for (int kh = 0; kh < 2; kh++) {
            int kc0 = kh * 2;
            uint32_t af[2][4], bf[4][4];
            #pragma unroll
            for (int am = 0; am < 2; am++) {
                int r = aR + am * 16;
                uint32_t ad = stb + GS_A + (uint32_t)(r * 64 + ((((kc0 + aKh) ^ ((r >> 1) & 3))) << 4));
                ldsm4(af[am], ad);
            }
            #pragma unroll
            for (int p = 0; p < 4; p++) {
                int n = bN + p * 16;
                uint32_t bd = stb + GS_B + (uint32_t)(n * 64 + ((((kc0 + bKh) ^ ((n >> 1) & 3))) << 4));
                ldsm4(bf[p], bd);
            }
            #pragma unroll
            for (int am = 0; am < 2; am++)
                #pragma unroll
                for (int t = 0; t < 8; t++)
                    mma_f16(acc[am][t], af[am], &bf[t >> 1][2 * (t & 1)]);
        }
        // no bottom barrier: next top barrier orders reads before overwrite
    }
#undef LOAD_STAGE

    #pragma unroll
    for (int am = 0; am < 2; am++) {
        int r = row0 + warp_m * 32 + am * 16 + (lane >> 2);
        #pragma unroll
        for (int t = 0; t < 8; t++) {
            int c = col0 + warp_n * 64 + t * 8 + (lane & 3) * 2;
            float2 bv = *(const float2*)(bias + c);
            float v0 = acc[am][t][0] + bv.x;
            float v1 = acc[am][t][1] + bv.y;
            float v2 = acc[am][t][2] + bv.x;
            float v3 = acc[am][t][3] + bv.y;
            if (mode == 0) {
                float2 w0 = {v0, v1}, w1 = {v2, v3};
                *(float2*)(Cf + (size_t)r * N + c)       = w0;
                *(float2*)(Cf + (size_t)(r + 8) * N + c) = w1;
            } else {
                v0 = geluf(v0); v1 = geluf(v1); v2 = geluf(v2); v3 = geluf(v3);
                __half2 p0 = __floats2half2_rn(v0, v1);
                __half2 p1 = __floats2half2_rn(v2, v3);
                *(uint32_t*)(Ch + (size_t)r * N + c)       = *(uint32_t*)&p0;
                *(uint32_t*)(Ch + (size_t)(r + 8) * N + c) = *(uint32_t*)&p1;
            }
        }
    }
}

// ---------------- proj prep ----------------
__global__ void prep_proj(const float* __restrict__ proj) {
    int i = blockIdx.x * 256 + threadIdx.x;
    if (i < HD * MF) {
        int d = i >> 8, m = i & 255;
        float v = proj[m * HD + d];
        uint32_t h = f2tf(v);
        g_projhi[i] = h;
        g_projlo[i] = f2tf(v - __uint_as_float(h));
    }
}
__global__ void kmax_init() { if (threadIdx.x < BH) g_kmax[threadIdx.x] = -3.4e38f; }

// ---------------- fused dash: proj loaded once, 4x32-row sub-tiles per block ----------------
#define DPH_OFF 0
#define DPL_OFF 67584
#define DAH_OFF 135168
#define DAL_OFF 143872
#define DSD_OFF 152576
#define DSM_OFF 152704
#define DWM_OFF 152832
#define DASH_SMEM 153856

extern "C" __global__ __launch_bounds__(256) void dash_fused(
    const float* __restrict__ data, int ldd, float* __restrict__ outp,
    float* __restrict__ kdiag, float* __restrict__ kmaxbuf, int isquery)
{
    extern __shared__ unsigned char dsm[];
    uint32_t (*Ph)[264] = (uint32_t(*)[264])(dsm + DPH_OFF);
    uint32_t (*Pl)[264] = (uint32_t(*)[264])(dsm + DPL_OFF);
    uint32_t (*Ah)[68]  = (uint32_t(*)[68])(dsm + DAH_OFF);
    uint32_t (*Al)[68]  = (uint32_t(*)[68])(dsm + DAL_OFF);
    float* sdiag = (float*)(dsm + DSD_OFF);
    float* smax  = (float*)(dsm + DSM_OFF);
    float* wmax  = (float*)(dsm + DWM_OFF);

    int bh = blockIdx.y, b = bh >> 4, h = bh & 15;
    int tid = threadIdx.x, lane = tid & 31, wid = tid >> 5;

    #pragma unroll
    for (int i = 0; i < 16; i++) {
        int cid = i * 256 + tid;
        int r = cid >> 6, c = (cid & 63) * 4;
        cpasync16(&Ph[r][c], g_projhi + r * 256 + c);
        cpasync16(&Pl[r][c], g_projlo + r * 256 + c);
    }
    cpcommit();
    cpwait0();
    __syncthreads();

    for (int st = 0; st < 4; st++) {
        int n0 = blockIdx.x * 128 + st * 32;

        {
            int r = tid >> 3, c0 = (tid & 7) * 8;
            const float* src = data + ((size_t)(b * SEQ + n0 + r)) * ldd + h * HD + c0;
            float4 v0 = *(const float4*)src;
            float4 v1 = *(const float4*)(src + 4);
            float ss = v0.x*v0.x + v0.y*v0.y + v0.z*v0.z + v0.w*v0.w
                     + v1.x*v1.x + v1.y*v1.y + v1.z*v1.z + v1.w*v1.w;
            ss += __shfl_xor_sync(~0u, ss, 1);
            ss += __shfl_xor_sync(~0u, ss, 2);
            ss += __shfl_xor_sync(~0u, ss, 4);
            if ((tid & 7) == 0) sdiag[r] = 0.0625f * ss;
            float a[8] = {v0.x,v0.y,v0.z,v0.w,v1.x,v1.y,v1.z,v1.w};
            #pragma unroll
            for (int j = 0; j < 8; j++) {
                float av = DATA_NORM * a[j];
                uint32_t hi = f2tf(av);
                Ah[r][c0+j] = hi;
                Al[r][c0+j] = f2tf(av - __uint_as_float(hi));
            }
        }
        __syncthreads();

        float acc[2][4][4];
        #pragma unroll
        for (int i = 0; i < 2; i++)
            #pragma unroll
            for (int j = 0; j < 4; j++)
                #pragma unroll
                for (int l = 0; l < 4; l++) acc[i][j][l] = 0.f;

        int ncol = wid * 32;
        #pragma unroll
        for (int k0 = 0; k0 < 64; k0 += 8) {
            uint32_t ah[2][4], al[2][4];
            #pragma unroll
            for (int mt = 0; mt < 2; mt++) {
                int r = mt * 16 + (lane >> 2), c = k0 + (lane & 3);
                ah[mt][0] = Ah[r][c];    ah[mt][1] = Ah[r+8][c];
                ah[mt][2] = Ah[r][c+4];  ah[mt][3] = Ah[r+8][c+4];
                al[mt][0] = Al[r][c];    al[mt][1] = Al[r+8][c];
                al[mt][2] = Al[r][c+4];  al[mt][3] = Al[r+8][c+4];
            }
            uint32_t bhf[4][2], blf[4][2];
            #pragma unroll
            for (int nt = 0; nt < 4; nt++) {
                int n = ncol + nt * 8 + (lane >> 2), kk = k0 + (lane & 3);
                bhf[nt][0] = Ph[kk][n];   bhf[nt][1] = Ph[kk+4][n];
                blf[nt][0] = Pl[kk][n];   blf[nt][1] = Pl[kk+4][n];
            }
            #pragma unroll
            for (int mt = 0; mt < 2; mt++)
                #pragma unroll
                for (int nt = 0; nt < 4; nt++) {
                    mma16n8k8(acc[mt][nt], ah[mt], bhf[nt]);
                    mma16n8k8(acc[mt][nt], ah[mt], blf[nt]);
                    mma16n8k8(acc[mt][nt], al[mt], bhf[nt]);
                }
        }

        #pragma unroll
        for (int mt = 0; mt < 2; mt++) {
            float m0 = -3.4e38f, m1 = -3.4e38f;
            #pragma unroll
            for (int nt = 0; nt < 4; nt++) {
                m0 = fmaxf(m0, fmaxf(acc[mt][nt][0], acc[mt][nt][1]));
                m1 = fmaxf(m1, fmaxf(acc[mt][nt][2], acc[mt][nt][3]));
            }
            m0 = fmaxf(m0, __shfl_xor_sync(~0u, m0, 1));
            m0 = fmaxf(m0, __shfl_xor_sync(~0u, m0, 2));
            m1 = fmaxf(m1, __shfl_xor_sync(~0u, m1, 1));
            m1 = fmaxf(m1, __shfl_xor_sync(~0u, m1, 2));
            if ((lane & 3) == 0) {
                wmax[wid * 32 + mt * 16 + (lane >> 2)]     = m0;
                wmax[wid * 32 + mt * 16 + 8 + (lane >> 2)] = m1;
            }
        }
        __syncthreads();
        if (tid < 32) {
            float mx = wmax[tid];
            #pragma unroll
            for (int w = 1; w < 8; w++) mx = fmaxf(mx, wmax[w * 32 + tid]);
            smax[tid] = mx;
        }
        __syncthreads();
        if (!isquery) {
            if (tid < 32) kdiag[(size_t)bh * SEQ + n0 + tid] = sdiag[tid];
            if (tid == 0) {
                float bm = smax[0];
                #pragma unroll
                for (int i = 1; i < 32; i++) bm = fmaxf(bm, smax[i]);
                atomicMaxF(&kmaxbuf[bh], bm);
            }
        }

        #pragma unroll
        for (int mt = 0; mt < 2; mt++) {
            int r = mt * 16 + (lane >> 2);
            #pragma unroll
            for (int nt = 0; nt < 4; nt++) {
                int c = ncol + nt * 8 + (lane & 3) * 2;
                float v0 = acc[mt][nt][0], v1 = acc[mt][nt][1];
                float v2 = acc[mt][nt][2], v3 = acc[mt][nt][3];
                if (isquery) {
                    float s0 = sdiag[r] + smax[r];
                    float s1 = sdiag[r+8] + smax[r+8];
                    v0 = RATIO * (__expf(v0 - s0) + KEPS);
                    v1 = RATIO * (__expf(v1 - s0) + KEPS);
                    v2 = RATIO * (__expf(v2 - s1) + KEPS);
                    v3 = RATIO * (__expf(v3 - s1) + KEPS);
                }
                float2 w0 = {v0, v1}, w1 = {v2, v3};
                *(float2*)(outp + ((size_t)bh * SEQ + n0 + r) * MF + c)     = w0;
                *(float2*)(outp + ((size_t)bh * SEQ + n0 + r + 8) * MF + c) = w1;
            }
        }
        __syncthreads();
    }
}

// ---------------- kv + ksum ----------------
#define KAS_OFF 0
#define KVS_OFF 40960
#define KSR_OFF 50176
#define KV_SMEM 54272

extern "C" __global__ __launch_bounds__(256) void kv_ksum_kernel(
    const float* __restrict__ Kraw, const float* __restrict__ V, int ldv)
{
    extern __shared__ unsigned char ksm[];
    float (*As)[256][20] = (float(*)[256][20])(ksm + KAS_OFF);
    float (*Vs)[16][72]  = (float(*)[16][72])(ksm + KVS_OFF);
    float (*sred)[256]   = (float(*)[256])(ksm + KSR_OFF);

    int bh = blockIdx.y, chunk = blockIdx.x;
    int b = bh >> 4, h = bh & 15;
    int tid = threadIdx.x, lane = tid & 31, wid = tid >> 5;
    int wm = wid & 3, wn = wid >> 2;

    float kmax = g_kmax[bh];
    const float* Kb  = Kraw + ((size_t)bh * SEQ + chunk * 512) * MF;
    const float* Vb  = V + ((size_t)(b * SEQ + chunk * 512)) * ldv + h * HD;
    const float* dgb = g_kdiag + (size_t)bh * SEQ + chunk * 512;

    int mcol = tid & 63;
    int nr   = tid >> 6;
    float ks[4] = {0.f, 0.f, 0.f, 0.f};

    float acc[4][4][4];
    #pragma unroll
    for (int i = 0; i < 4; i++)
        #pragma unroll
        for (int j = 0; j < 4; j++)
            #pragma unroll
            for (int l = 0; l < 4; l++) acc[i][j][l] = 0.f;

#define LOAD_TILE(nt, buf)                                                        \
    {                                                                             \
        _Pragma("unroll")                                                         \
        for (int p = 0; p < 4; p++) {                                             \
            int nl = p * 4 + nr;                                                  \
            int ng = (nt) * 16 + nl;                                              \
            float dg = dgb[ng] + kmax;                                            \
            const float* kr = Kb + (size_t)ng * MF + mcol;                        \
            float r0 = kr[0], r1 = kr[64], r2 = kr[128], r3 = kr[192];            \
            float e0 = trunctf(RATIO * (__expf(r0 - dg) + KEPS));                 \
            float e1 = trunctf(RATIO * (__expf(r1 - dg) + KEPS));                 \
            float e2 = trunctf(RATIO * (__expf(r2 - dg) + KEPS));                 \
            float e3 = trunctf(RATIO * (__expf(r3 - dg) + KEPS));                 \
            ks[0] += e0; ks[1] += e1; ks[2] += e2; ks[3] += e3;                   \
            As[buf][mcol][nl] = e0;   As[buf][mcol+64][nl] = e1;                  \
            As[buf][mcol+128][nl] = e2; As[buf][mcol+192][nl] = e3;               \
        }                                                                         \
        cpasync16(&Vs[buf][tid >> 4][(tid & 15) * 4],                             \
                  Vb + (size_t)((nt) * 16 + (tid >> 4)) * ldv + (tid & 15) * 4);  \
        cpcommit();                                                               \
    }

    LOAD_TILE(0, 0);

    for (int nt = 0; nt < 32; nt++) {
        int buf = nt & 1;
        cpwait0();
        __syncthreads();
        if (nt + 1 < 32) LOAD_TILE(nt + 1, buf ^ 1);

        const uint32_t (*Au)[20] = (const uint32_t(*)[20])As[buf];
        const uint32_t (*Vu)[72] = (const uint32_t(*)[72])Vs[buf];

        #pragma unroll
        for (int ks2 = 0; ks2 < 2; ks2++) {
            int k0 = ks2 * 8;
            uint32_t a[4][4];
            #pragma unroll
            for (int mt = 0; mt < 4; mt++) {
                int r = wm * 64 + mt * 16 + (lane >> 2), c = k0 + (lane & 3);
                a[mt][0] = Au[r][c];
                a[mt][1] = Au[r+8][c];
                a[mt][2] = Au[r][c+4];
                a[mt][3] = Au[r+8][c+4];
            }
            uint32_t bb[4][2];
            #pragma unroll
            for (int dt = 0; dt < 4; dt++) {
                int n = wn * 32 + dt * 8 + (lane >> 2), kk = k0 + (lane & 3);
                bb[dt][0] = Vu[kk][n];
                bb[dt][1] = Vu[kk+4][n];
            }
            #pragma unroll
            for (int mt = 0; mt < 4; mt++)
                #pragma unroll
                for (int dt = 0; dt < 4; dt++)
                    mma16n8k8(acc[mt][dt], a[mt], bb[dt]);
        }
    }
#undef LOAD_TILE

    float* kvp = g_kvpart + ((size_t)(bh * NCHUNK + chunk)) * MF * HD;
    #pragma unroll
    for (int mt = 0; mt < 4; mt++) {
        int m = wm * 64 + mt * 16 + (lane >> 2);
        #pragma unroll
        for (int dt = 0; dt < 4; dt++) {
            int d = wn * 32 + dt * 8 + (lane & 3) * 2;
            float2 w0 = {acc[mt][dt][0], acc[mt][dt][1]};
            float2 w1 = {acc[mt][dt][2], acc[mt][dt][3]};
            *(float2*)(kvp + (size_t)m * HD + d)       = w0;
            *(float2*)(kvp + (size_t)(m + 8) * HD + d) = w1;
        }
    }
    __syncthreads();
    sred[nr][mcol]       = ks[0];
    sred[nr][mcol + 64]  = ks[1];
    sred[nr][mcol + 128] = ks[2];
    sred[nr][mcol + 192] = ks[3];
    __syncthreads();
    float s = sred[0][tid & 255] + sred[1][tid & 255] + sred[2][tid & 255] + sred[3][tid & 255];
    g_kspart[(size_t)(bh * NCHUNK + chunk) * MF + tid] = s;
}

// ---------------- reduce partials ----------------
__global__ __launch_bounds__(256) void kv_reduce() {
    int bh = blockIdx.x, tid = threadIdx.x;
    for (int i = tid; i < MF * HD; i += 256) {
        float s = 0.f;
        #pragma unroll
        for (int c = 0; c < NCHUNK; c++)
            s += g_kvpart[((size_t)(bh * NCHUNK + c)) * MF * HD + i];
        g_kv[(size_t)bh * MF * HD + i] = s;
    }
    float s = 0.f;
    #pragma unroll
    for (int c = 0; c < NCHUNK; c++)
        s += g_kspart[(size_t)(bh * NCHUNK + c) * MF + tid];
    g_ksum[bh * MF + tid] = s;
}

// ---------------- attn + denom fused ----------------
__global__ __launch_bounds__(256) void attn_fused(
    const float* __restrict__ Qp, float* __restrict__ out)
{
    __shared__ float Qs[2][128][20];
    __shared__ float Bs[2][16][72];
    __shared__ float sk[256];
    __shared__ float sdn[128];

    int bh = blockIdx.y, b = bh >> 4, h = bh & 15;
    int n0 = blockIdx.x * 128;
    int tid = threadIdx.x, lane = tid & 31, wid = tid >> 5;
    int wm = wid & 3, wn = wid >> 2;

    sk[tid] = g_ksum[bh * MF + tid];

    const float* Qb = Qp + ((size_t)bh * SEQ + n0) * MF;
    const float* Vb = g_kv + (size_t)bh * MF * HD;

#define LOADQ(kt, buf)                                                        \
    {                                                                         \
        _Pragma("unroll")                                                     \
        for (int i = 0; i < 2; i++) {                                         \
            int cid = i * 256 + tid;                                          \
            int r = cid >> 2, c = (cid & 3) * 4;                              \
            cpasync16(&Qs[buf][r][c], Qb + (size_t)r * MF + (kt) * 16 + c);   \
        }                                                                     \
        cpasync16(&Bs[buf][tid >> 4][(tid & 15) * 4],                         \
                  Vb + (size_t)((kt) * 16 + (tid >> 4)) * HD + (tid & 15) * 4); \
        cpcommit();                                                           \
    }

    LOADQ(0, 0);

    float acc[2][4][4];
    #pragma unroll
    for (int i = 0; i < 2; i++)
        #pragma unroll
        for (int j = 0; j < 4; j++)
            #pragma unroll
            for (int l = 0; l < 4; l++) acc[i][j][l] = 0.f;
    float dn = 0.f;

    for (int kt = 0; kt < 16; kt++) {
        int buf = kt & 1;
        cpwait0();
        __syncthreads();
        if (kt + 1 < 16) LOADQ(kt + 1, buf ^ 1);

        if (tid < 128) {
            #pragma unroll
            for (int j = 0; j < 16; j++) dn += trunctf(Qs[buf][tid][j]) * sk[kt * 16 + j];
        }

        const uint32_t (*Qu)[20] = (const uint32_t(*)[20])Qs[buf];
        const uint32_t (*Bu)[72] = (const uint32_t(*)[72])Bs[buf];

        #pragma unroll
        for (int ks2 = 0; ks2 < 2; ks2++) {
            int k0 = ks2 * 8;
            uint32_t a[2][4];
            #pragma unroll
            for (int mt = 0; mt < 2; mt++) {
                int r = wm * 32 + mt * 16 + (lane >> 2), c = k0 + (lane & 3);
                a[mt][0] = Qu[r][c];
                a[mt][1] = Qu[r+8][c];
                a[mt][2] = Qu[r][c+4];
                a[mt][3] = Qu[r+8][c+4];
            }
            uint32_t bb[4][2];
            #pragma unroll
            for (int dt = 0; dt < 4; dt++) {
                int n = wn * 32 + dt * 8 + (lane >> 2), kk = k0 + (lane & 3);
                bb[dt][0] = Bu[kk][n];
                bb[dt][1] = Bu[kk+4][n];
            }
            #pragma unroll
            for (int mt = 0; mt < 2; mt++)
                #pragma unroll
                for (int dt = 0; dt < 4; dt++)
                    mma16n8k8(acc[mt][dt], a[mt], bb[dt]);
        }
    }
#undef LOADQ

    if (tid < 128) sdn[tid] = dn;
    __syncthreads();

    #pragma unroll
    for (int mt = 0; mt < 2; mt++) {
        int r = wm * 32 + mt * 16 + (lane >> 2);
        float i0 = 1.f / sdn[r];
        float i1 = 1.f / sdn[r + 8];
        #pragma unroll
        for (int dt = 0; dt < 4; dt++) {
            int c = wn * 32 + dt * 8 + (lane & 3) * 2;
            float2 w0 = {acc[mt][dt][0] * i0, acc[mt][dt][1] * i0};
            float2 w1 = {acc[mt][dt][2] * i1, acc[mt][dt][3] * i1};
            *(float2*)(out + ((size_t)(b * SEQ + n0 + r)) * DMODEL + h * HD + c)     = w0;
            *(float2*)(out + ((size_t)(b * SEQ + n0 + r + 8)) * DMODEL + h * HD + c) = w1;
        }
    }
}

// ---------------- fused residual + LayerNorm ----------------
__global__ __launch_bounds__(256) void ln_kernel(
    const float* __restrict__ a, const float* __restrict__ res,
    const float* __restrict__ gam, const float* __restrict__ bet, float* __restrict__ out)
{
    __shared__ float red[8];
    int row = blockIdx.x, tid = threadIdx.x;
    int lane = tid & 31, w = tid >> 5;
    size_t base = (size_t)row * DMODEL + tid * 4;
    float4 v = *(const float4*)(a + base);
    float4 r = *(const float4*)(res + base);
    v.x += r.x; v.y += r.y; v.z += r.z; v.w += r.w;

    float s = v.x + v.y + v.z + v.w;
    #pragma unroll
    for (int o = 16; o; o >>= 1) s += __shfl_xor_sync(0xffffffffu, s, o);
    if (lane == 0) red[w] = s;
    __syncthreads();
    float t = (tid < 8) ? red[tid] : 0.f;
    if (w == 0) {
        #pragma unroll
        for (int o = 4; o; o >>= 1) t += __shfl_xor_sync(0xffffffffu, t, o);
        if (lane == 0) red[0] = t;
    }
    __syncthreads();
    float mean = red[0] * (1.f / DMODEL);
    __syncthreads();

    float d0 = v.x - mean, d1 = v.y - mean, d2 = v.z - mean, d3 = v.w - mean;
    float s2 = d0*d0 + d1*d1 + d2*d2 + d3*d3;
    #pragma unroll
    for (int o = 16; o; o >>= 1) s2 += __shfl_xor_sync(0xffffffffu, s2, o);
    if (lane == 0) red[w] = s2;
    __syncthreads();
    float t2 = (tid < 8) ? red[tid] : 0.f;
    if (w == 0) {
        #pragma unroll
        for (int o = 4; o; o >>= 1) t2 += __shfl_xor_sync(0xffffffffu, t2, o);
        if (lane == 0) red[0] = t2;
    }
    __syncthreads();
    float var = red[0] * (1.f / DMODEL);
    float inv = rsqrtf(var + LNEPS);

    float4 g4 = *(const float4*)(gam + tid * 4);
    float4 b4 = *(const float4*)(bet + tid * 4);
    float4 o4;
    o4.x = d0 * inv * g4.x + b4.x;
    o4.y = d1 * inv * g4.y + b4.y;
    o4.z = d2 * inv * g4.z + b4.z;
    o4.w = d3 * inv * g4.w + b4.w;
    *(float4*)(out + base) = o4;
}

// ---------------- launch ----------------
extern "C" void kernel_launch(void* const* d_in, const int* in_sizes, int n_in,
                              void* d_out, int out_size)
{
    const float* x  = (const float*)d_in[0];
    const float* wq = (const float*)d_in[1];  const float* bq = (const float*)d_in[2];
    const float* wk = (const float*)d_in[3];  const float* bk = (const float*)d_in[4];
    const float* wv = (const float*)d_in[5];  const float* bv = (const float*)d_in[6];
    const float* wo = (const float*)d_in[7];  const float* bo = (const float*)d_in[8];
    const float* proj = (const float*)d_in[9];
    const float* w1 = (const float*)d_in[10]; const float* b1 = (const float*)d_in[11];
    const float* w2 = (const float*)d_in[12]; const float* b2 = (const float*)d_in[13];
    const float* ln1g = (const float*)d_in[14]; const float* ln1b = (const float*)d_in[15];
    const float* ln2g = (const float*)d_in[16]; const float* ln2b = (const float*)d_in[17];
    float* out = (float*)d_out;

    static int attr_done = 0;
    if (!attr_done) {
        cudaFuncSetAttribute(fp16_gemm, cudaFuncAttributeMaxDynamicSharedMemorySize, GEMM_SMEM);
        cudaFuncSetAttribute(dash_fused, cudaFuncAttributeMaxDynamicSharedMemorySize, DASH_SMEM);
        cudaFuncSetAttribute(kv_ksum_kernel, cudaFuncAttributeMaxDynamicSharedMemorySize, KV_SMEM);
        attr_done = 1;
    }

    float *QKV, *bqkv, *Qp, *Kp, *kdiag, *kmax, *attn, *x1, *t;
    cudaGetSymbolAddress((void**)&QKV, g_QKV);
    cudaGetSymbolAddress((void**)&bqkv, g_bqkv);
    cudaGetSymbolAddress((void**)&Qp, g_Qp);
    cudaGetSymbolAddress((void**)&Kp, g_Kp);
    cudaGetSymbolAddress((void**)&kdiag, g_kdiag);
    cudaGetSymbolAddress((void**)&kmax, g_kmax);
    cudaGetSymbolAddress((void**)&attn, g_attn);
    cudaGetSymbolAddress((void**)&x1, g_x1);
    cudaGetSymbolAddress((void**)&t,  g_t);

    __half *x16,*a16,*x116,*h16,*wqkvT16,*woT16,*w1T16,*w2T16;
    cudaGetSymbolAddress((void**)&x16, g_x16);
    cudaGetSymbolAddress((void**)&a16, g_a16);
    cudaGetSymbolAddress((void**)&x116, g_x116);
    cudaGetSymbolAddress((void**)&h16, g_h16);
    cudaGetSymbolAddress((void**)&wqkvT16, g_wqkvT16);
    cudaGetSymbolAddress((void**)&woT16, g_woT16);
    cudaGetSymbolAddress((void**)&w1T16, g_w1T16);
    cudaGetSymbolAddress((void**)&w2T16, g_w2T16);

    prep_proj<<<64, 256>>>(proj);
    kmax_init<<<1, 64>>>();
    pack_bias<<<4, 256>>>(bq, bk, bv);

    // weight transpose + fp16 convert: wqkvT rows 0..1023=Q, 1024..2047=K, 2048..3071=V
    wt_conv_h<<<dim3(32, 32), 256>>>(wq, wqkvT16,               DMODEL, DMODEL);
    wt_conv_h<<<dim3(32, 32), 256>>>(wk, wqkvT16 + 1024*1024,   DMODEL, DMODEL);
    wt_conv_h<<<dim3(32, 32), 256>>>(wv, wqkvT16 + 2*1024*1024, DMODEL, DMODEL);
    wt_conv_h<<<dim3(32, 32), 256>>>(wo, woT16, DMODEL, DMODEL);
    wt_conv_h<<<dim3(DFF/32, DMODEL/32), 256>>>(w1, w1T16, DMODEL, DFF);
    wt_conv_h<<<dim3(DMODEL/32, DFF/32), 256>>>(w2, w2T16, DFF, DMODEL);
    conv_act_h<<<ROWS*DMODEL/4/256, 256>>>(x, x16, ROWS*DMODEL/4);

    // QKV fused GEMM (N=3072)
    fp16_gemm<<<dim3(D3/128, ROWS/128), 256, GEMM_SMEM>>>(
        x16, wqkvT16, bqkv, QKV, nullptr, ROWS, D3, DMODEL, 0);

    dim3 gdash(SEQ/128, BH);
    dash_fused<<<gdash, 256, DASH_SMEM>>>(QKV, D3, Qp, nullptr, nullptr, 1);
    dash_fused<<<gdash, 256, DASH_SMEM>>>(QKV + 1024, D3, Kp, kdiag, kmax, 0);

    kv_ksum_kernel<<<dim3(NCHUNK, BH), 256, KV_SMEM>>>(Kp, QKV + 2048, D3);
    kv_reduce<<<BH, 256>>>();
    attn_fused<<<dim3(SEQ/128, BH), 256>>>(Qp, attn);

    conv_act_h<<<ROWS*DMODEL/4/256, 256>>>(attn, a16, ROWS*DMODEL/4);
    fp16_gemm<<<dim3(DMODEL/128, ROWS/128), 256, GEMM_SMEM>>>(
        a16, woT16, bo, t, nullptr, ROWS, DMODEL, DMODEL, 0);
    ln_kernel<<<ROWS, 256>>>(t, x, ln1g, ln1b, x1);
    conv_act_h<<<ROWS*DMODEL/4/256, 256>>>(x1, x116, ROWS*DMODEL/4);

    fp16_gemm<<<dim3(DFF/128, ROWS/128), 256, GEMM_SMEM>>>(
        x116, w1T16, b1, nullptr, h16, ROWS, DFF, DMODEL, 1);
    fp16_gemm<<<dim3(DMODEL/128, ROWS/128), 256, GEMM_SMEM>>>(
        h16, w2T16, b2, t, nullptr, ROWS, DMODEL, DFF, 0);
    ln_kernel<<<ROWS, 256>>>(t, x1, ln2g, ln2b, out);
}

// round 17
// speedup vs baseline: 2.0074x; 1.0459x over previous
#include <cuda_runtime.h>
#include <cuda_fp16.h>
#include <math.h>
#include <stdint.h>

#define BB 4
#define SEQ 4096
#define DMODEL 1024
#define NHEAD 16
#define HD 64
#define MF 256
#define DFF 4096
#define ROWS (BB*SEQ)
#define BH (BB*NHEAD)
#define NCHUNK 8
#define D3 (3*DMODEL)

#define DATA_NORM 0.35355339059327373f
#define RATIO     0.0625f
#define KEPS      1e-4f
#define LNEPS     1e-5f

// ---------------- scratch ----------------
__device__ float g_QKV[(size_t)ROWS*D3];
__device__ float g_bqkv[D3];
__device__ __half g_Qp16[(size_t)BH*SEQ*MF];
__device__ float g_Kp[(size_t)BH*SEQ*MF];
__device__ float g_kdiag[(size_t)BH*SEQ];
__device__ float g_kmax[BH];
__device__ float g_kvpart[(size_t)BH*NCHUNK*MF*HD];
__device__ float g_kspart[(size_t)BH*NCHUNK*MF];
__device__ __half g_kvT16[(size_t)BH*HD*MF];
__device__ float g_ksum[BH*MF];
__device__ float g_x1[(size_t)ROWS*DMODEL];
__device__ float g_t[(size_t)ROWS*DMODEL];
__device__ uint32_t g_projhi[HD*MF];
__device__ uint32_t g_projlo[HD*MF];

// fp16 operands
__device__ __half g_x16[(size_t)ROWS*DMODEL];
__device__ __half g_a16[(size_t)ROWS*DMODEL];
__device__ __half g_x116[(size_t)ROWS*DMODEL];
__device__ __half g_h16[(size_t)ROWS*DFF];
__device__ __half g_wqkvT16[(size_t)D3*DMODEL];
__device__ __half g_woT16[DMODEL*DMODEL];
__device__ __half g_w1T16[(size_t)DFF*DMODEL];
__device__ __half g_w2T16[(size_t)DMODEL*DFF];

// ---------------- helpers ----------------
__device__ __forceinline__ float geluf(float x) {
    return 0.5f * x * (1.f + erff(x * 0.7071067811865476f));
}
__device__ __forceinline__ void atomicMaxF(float* addr, float v) {
    int old = __float_as_int(*addr);
    while (__int_as_float(old) < v) {
        int prev = atomicCAS((int*)addr, old, __float_as_int(v));
        if (prev == old) break;
        old = prev;
    }
}
__device__ __forceinline__ uint32_t f2tf(float f) {
    uint32_t r;
    asm("cvt.rna.tf32.f32 %0, %1;" : "=r"(r) : "f"(f));
    return r;
}
__device__ __forceinline__ float trunctf(float f) {
    return __uint_as_float(__float_as_uint(f) & 0xffffe000u);
}
__device__ __forceinline__ void mma16n8k8(float* c, const uint32_t* a, const uint32_t* b) {
    asm volatile(
        "mma.sync.aligned.m16n8k8.row.col.f32.tf32.tf32.f32 "
        "{%0,%1,%2,%3}, {%4,%5,%6,%7}, {%8,%9}, {%0,%1,%2,%3};"
        : "+f"(c[0]), "+f"(c[1]), "+f"(c[2]), "+f"(c[3])
        : "r"(a[0]), "r"(a[1]), "r"(a[2]), "r"(a[3]), "r"(b[0]), "r"(b[1]));
}
__device__ __forceinline__ void mma_f16(float* c, const uint32_t* a, const uint32_t* b) {
    asm volatile(
        "mma.sync.aligned.m16n8k16.row.col.f32.f16.f16.f32 "
        "{%0,%1,%2,%3}, {%4,%5,%6,%7}, {%8,%9}, {%0,%1,%2,%3};"
        : "+f"(c[0]), "+f"(c[1]), "+f"(c[2]), "+f"(c[3])
        : "r"(a[0]), "r"(a[1]), "r"(a[2]), "r"(a[3]), "r"(b[0]), "r"(b[1]));
}
__device__ __forceinline__ void ldsm4(uint32_t* r, uint32_t addr) {
    asm volatile("ldmatrix.sync.aligned.m8n8.x4.shared.b16 {%0,%1,%2,%3}, [%4];"
        : "=r"(r[0]), "=r"(r[1]), "=r"(r[2]), "=r"(r[3]) : "r"(addr));
}
__device__ __forceinline__ void cpasync16(void* s, const void* g) {
    uint32_t saddr = (uint32_t)__cvta_generic_to_shared(s);
    asm volatile("cp.async.cg.shared.global [%0], [%1], 16;" :: "r"(saddr), "l"(g));
}
__device__ __forceinline__ void cpasync16a(uint32_t saddr, const void* g) {
    asm volatile("cp.async.cg.shared.global [%0], [%1], 16;" :: "r"(saddr), "l"(g));
}
__device__ __forceinline__ void cpcommit() { asm volatile("cp.async.commit_group;"); }
__device__ __forceinline__ void cpwait0()  { asm volatile("cp.async.wait_group 0;"); }
__device__ __forceinline__ void cpwait1()  { asm volatile("cp.async.wait_group 1;"); }

// ---------------- conversions ----------------
__global__ __launch_bounds__(256) void conv_act_h(
    const float* __restrict__ src, __half* __restrict__ dst, int n4)
{
    int i = blockIdx.x * 256 + threadIdx.x;
    if (i >= n4) return;
    float4 v = ((const float4*)src)[i];
    __half2 p0 = __floats2half2_rn(v.x, v.y);
    __half2 p1 = __floats2half2_rn(v.z, v.w);
    uint2 u = {*(uint32_t*)&p0, *(uint32_t*)&p1};
    ((uint2*)dst)[i] = u;
}
__global__ __launch_bounds__(256) void wt_conv_h(
    const float* __restrict__ src, __half* __restrict__ dst, int K, int N)
{
    __shared__ float tile[32][33];
    int n0 = blockIdx.x * 32, k0 = blockIdx.y * 32;
    int tid = threadIdx.x;
    int c = tid & 31, r0 = (tid >> 5) * 4;
    #pragma unroll
    for (int rr = 0; rr < 4; rr++)
        tile[r0 + rr][c] = src[(size_t)(k0 + r0 + rr) * N + n0 + c];
    __syncthreads();
    int j = tid & 31, i0 = (tid >> 5) * 4;
    #pragma unroll
    for (int ii = 0; ii < 4; ii++)
        dst[(size_t)(n0 + i0 + ii) * K + k0 + j] = __float2half_rn(tile[j][i0 + ii]);
}
__global__ void pack_bias(const float* bq, const float* bk, const float* bv) {
    int i = blockIdx.x * 256 + threadIdx.x;
    if (i < DMODEL) {
        g_bqkv[i] = bq[i];
        g_bqkv[1024 + i] = bk[i];
        g_bqkv[2048 + i] = bv[i];
    }
}

// ---------------- fp16 GEMM: 128x128xBK32, 3-stage, swizzled ldmatrix ----------------
#define GS_A 0
#define GS_B 8192
#define GS_STAGE 16384
#define GEMM_SMEM (3*GS_STAGE)

__global__ __launch_bounds__(256, 2) void fp16_gemm(
    const __half* __restrict__ A_, const __half* __restrict__ B_,
    const float* __restrict__ bias, float* __restrict__ Cf,
    __half* __restrict__ Ch, int M, int N, int K, int mode)
{
    extern __shared__ char gsm[];
    uint32_t sb = (uint32_t)__cvta_generic_to_shared(gsm);

    int tid = threadIdx.x, lane = tid & 31, wid = tid >> 5;
    int warp_m = wid & 3, warp_n = wid >> 2;
    int row0 = blockIdx.y * 128, col0 = blockIdx.x * 128;

    int lrow = tid >> 2, lc = tid & 3;
    int aR = warp_m * 32 + (lane & 15);
    int aKh = lane >> 4;
    int bN  = warp_n * 64 + (lane & 7) + ((lane >> 4) & 1) * 8;
    int bKh = (lane >> 3) & 1;

    float acc[2][8][4];
    #pragma unroll
    for (int i = 0; i < 2; i++)
        #pragma unroll
        for (int j = 0; j < 8; j++)
            #pragma unroll
            for (int l = 0; l < 4; l++) acc[i][j][l] = 0.f;

    int nk = K >> 5;

#define LOAD_STAGE(kt, st)                                                            \
    {                                                                                 \
        uint32_t stb = sb + (st) * GS_STAGE;                                          \
        int kc = (kt) * 32;                                                           \
        _Pragma("unroll")                                                             \
        for (int i = 0; i < 2; i++) {                                                 \
            int row = lrow + i * 64;                                                  \
            uint32_t so = (uint32_t)(row * 64 + ((lc ^ ((row >> 1) & 3)) << 4));      \
            cpasync16a(stb + GS_A + so, A_ + (size_t)(row0 + row) * K + kc + lc * 8); \
            cpasync16a(stb + GS_B + so, B_ + (size_t)(col0 + row) * K + kc + lc * 8); \
        }                                                                             \
    }

    LOAD_STAGE(0, 0); cpcommit();
    LOAD_STAGE(1, 1); cpcommit();

    for (int kt = 0; kt < nk; kt++) {
        int cur = kt % 3;
        cpwait1();
        __syncthreads();

        if (kt + 2 < nk) LOAD_STAGE(kt + 2, (kt + 2) % 3);
        cpcommit();

        uint32_t stb = sb + cur * GS_STAGE;

        #pragma unroll
        for (int kh = 0; kh < 2; kh++) {
            int kc0 = kh * 2;
            uint32_t af[2][4], bf[4][4];
            #pragma unroll
            for (int am = 0; am < 2; am++) {
                int r = aR + am * 16;
                ldsm4(af[am], stb + GS_A + (uint32_t)(r * 64 + ((((kc0 + aKh) ^ ((r >> 1) & 3))) << 4)));
            }
            #pragma unroll
            for (int p = 0; p < 4; p++) {
                int n = bN + p * 16;
                ldsm4(bf[p], stb + GS_B + (uint32_t)(n * 64 + ((((kc0 + bKh) ^ ((n >> 1) & 3))) << 4)));
            }
            #pragma unroll
            for (int am = 0; am < 2; am++)
                #pragma unroll
                for (int t = 0; t < 8; t++)
                    mma_f16(acc[am][t], af[am], &bf[t >> 1][2 * (t & 1)]);
        }
    }
#undef LOAD_STAGE

    #pragma unroll
    for (int am = 0; am < 2; am++) {
        int r = row0 + warp_m * 32 + am * 16 + (lane >> 2);
        #pragma unroll
        for (int t = 0; t < 8; t++) {
            int c = col0 + warp_n * 64 + t * 8 + (lane & 3) * 2;
            float2 bv = *(const float2*)(bias + c);
            float v0 = acc[am][t][0] + bv.x;
            float v1 = acc[am][t][1] + bv.y;
            float v2 = acc[am][t][2] + bv.x;
            float v3 = acc[am][t][3] + bv.y;
            if (mode == 0) {
                float2 w0 = {v0, v1}, w1 = {v2, v3};
                *(float2*)(Cf + (size_t)r * N + c)       = w0;
                *(float2*)(Cf + (size_t)(r + 8) * N + c) = w1;
            } else {
                v0 = geluf(v0); v1 = geluf(v1); v2 = geluf(v2); v3 = geluf(v3);
                __half2 p0 = __floats2half2_rn(v0, v1);
                __half2 p1 = __floats2half2_rn(v2, v3);
                *(uint32_t*)(Ch + (size_t)r * N + c)       = *(uint32_t*)&p0;
                *(uint32_t*)(Ch + (size_t)(r + 8) * N + c) = *(uint32_t*)&p1;
            }
        }
    }
}

// ---------------- proj prep ----------------
__global__ void prep_proj(const float* __restrict__ proj) {
    int i = blockIdx.x * 256 + threadIdx.x;
    if (i < HD * MF) {
        int d = i >> 8, m = i & 255;
        float v = proj[m * HD + d];
        uint32_t h = f2tf(v);
        g_projhi[i] = h;
        g_projlo[i] = f2tf(v - __uint_as_float(h));
    }
}
__global__ void kmax_init() { if (threadIdx.x < BH) g_kmax[threadIdx.x] = -3.4e38f; }

// ---------------- fused dash (query writes fp16 Qp; key writes fp32 raw) ----------------
#define DPH_OFF 0
#define DPL_OFF 67584
#define DAH_OFF 135168
#define DAL_OFF 143872
#define DSD_OFF 152576
#define DSM_OFF 152704
#define DWM_OFF 152832
#define DASH_SMEM 153856

extern "C" __global__ __launch_bounds__(256) void dash_fused(
    const float* __restrict__ data, int ldd, float* __restrict__ outp,
    __half* __restrict__ outh,
    float* __restrict__ kdiag, float* __restrict__ kmaxbuf, int isquery)
{
    extern __shared__ unsigned char dsm[];
    uint32_t (*Ph)[264] = (uint32_t(*)[264])(dsm + DPH_OFF);
    uint32_t (*Pl)[264] = (uint32_t(*)[264])(dsm + DPL_OFF);
    uint32_t (*Ah)[68]  = (uint32_t(*)[68])(dsm + DAH_OFF);
    uint32_t (*Al)[68]  = (uint32_t(*)[68])(dsm + DAL_OFF);
    float* sdiag = (float*)(dsm + DSD_OFF);
    float* smax  = (float*)(dsm + DSM_OFF);
    float* wmax  = (float*)(dsm + DWM_OFF);

    int bh = blockIdx.y, b = bh >> 4, h = bh & 15;
    int tid = threadIdx.x, lane = tid & 31, wid = tid >> 5;

    #pragma unroll
    for (int i = 0; i < 16; i++) {
        int cid = i * 256 + tid;
        int r = cid >> 6, c = (cid & 63) * 4;
        cpasync16(&Ph[r][c], g_projhi + r * 256 + c);
        cpasync16(&Pl[r][c], g_projlo + r * 256 + c);
    }
    cpcommit();
    cpwait0();
    __syncthreads();

    for (int st = 0; st < 4; st++) {
        int n0 = blockIdx.x * 128 + st * 32;

        {
            int r = tid >> 3, c0 = (tid & 7) * 8;
            const float* src = data + ((size_t)(b * SEQ + n0 + r)) * ldd + h * HD + c0;
            float4 v0 = *(const float4*)src;
            float4 v1 = *(const float4*)(src + 4);
            float ss = v0.x*v0.x + v0.y*v0.y + v0.z*v0.z + v0.w*v0.w
                     + v1.x*v1.x + v1.y*v1.y + v1.z*v1.z + v1.w*v1.w;
            ss += __shfl_xor_sync(~0u, ss, 1);
            ss += __shfl_xor_sync(~0u, ss, 2);
            ss += __shfl_xor_sync(~0u, ss, 4);
            if ((tid & 7) == 0) sdiag[r] = 0.0625f * ss;
            float a[8] = {v0.x,v0.y,v0.z,v0.w,v1.x,v1.y,v1.z,v1.w};
            #pragma unroll
            for (int j = 0; j < 8; j++) {
                float av = DATA_NORM * a[j];
                uint32_t hi = f2tf(av);
                Ah[r][c0+j] = hi;
                Al[r][c0+j] = f2tf(av - __uint_as_float(hi));
            }
        }
        __syncthreads();

        float acc[2][4][4];
        #pragma unroll
        for (int i = 0; i < 2; i++)
            #pragma unroll
            for (int j = 0; j < 4; j++)
                #pragma unroll
                for (int l = 0; l < 4; l++) acc[i][j][l] = 0.f;

        int ncol = wid * 32;
        #pragma unroll
        for (int k0 = 0; k0 < 64; k0 += 8) {
            uint32_t ah[2][4], al[2][4];
            #pragma unroll
            for (int mt = 0; mt < 2; mt++) {
                int r = mt * 16 + (lane >> 2), c = k0 + (lane & 3);
                ah[mt][0] = Ah[r][c];    ah[mt][1] = Ah[r+8][c];
                ah[mt][2] = Ah[r][c+4];  ah[mt][3] = Ah[r+8][c+4];
                al[mt][0] = Al[r][c];    al[mt][1] = Al[r+8][c];
                al[mt][2] = Al[r][c+4];  al[mt][3] = Al[r+8][c+4];
            }
            uint32_t bhf[4][2], blf[4][2];
            #pragma unroll
            for (int nt = 0; nt < 4; nt++) {
                int n = ncol + nt * 8 + (lane >> 2), kk = k0 + (lane & 3);
                bhf[nt][0] = Ph[kk][n];   bhf[nt][1] = Ph[kk+4][n];
                blf[nt][0] = Pl[kk][n];   blf[nt][1] = Pl[kk+4][n];
            }
            #pragma unroll
            for (int mt = 0; mt < 2; mt++)
                #pragma unroll
                for (int nt = 0; nt < 4; nt++) {
                    mma16n8k8(acc[mt][nt], ah[mt], bhf[nt]);
                    mma16n8k8(acc[mt][nt], ah[mt], blf[nt]);
                    mma16n8k8(acc[mt][nt], al[mt], bhf[nt]);
                }
        }

        #pragma unroll
        for (int mt = 0; mt < 2; mt++) {
            float m0 = -3.4e38f, m1 = -3.4e38f;
            #pragma unroll
            for (int nt = 0; nt < 4; nt++) {
                m0 = fmaxf(m0, fmaxf(acc[mt][nt][0], acc[mt][nt][1]));
                m1 = fmaxf(m1, fmaxf(acc[mt][nt][2], acc[mt][nt][3]));
            }
            m0 = fmaxf(m0, __shfl_xor_sync(~0u, m0, 1));
            m0 = fmaxf(m0, __shfl_xor_sync(~0u, m0, 2));
            m1 = fmaxf(m1, __shfl_xor_sync(~0u, m1, 1));
            m1 = fmaxf(m1, __shfl_xor_sync(~0u, m1, 2));
            if ((lane & 3) == 0) {
                wmax[wid * 32 + mt * 16 + (lane >> 2)]     = m0;
                wmax[wid * 32 + mt * 16 + 8 + (lane >> 2)] = m1;
            }
        }
        __syncthreads();
        if (tid < 32) {
            float mx = wmax[tid];
            #pragma unroll
            for (int w = 1; w < 8; w++) mx = fmaxf(mx, wmax[w * 32 + tid]);
            smax[tid] = mx;
        }
        __syncthreads();
        if (!isquery) {
            if (tid < 32) kdiag[(size_t)bh * SEQ + n0 + tid] = sdiag[tid];
            if (tid == 0) {
                float bm = smax[0];
                #pragma unroll
                for (int i = 1; i < 32; i++) bm = fmaxf(bm, smax[i]);
                atomicMaxF(&kmaxbuf[bh], bm);
            }
        }

        #pragma unroll
        for (int mt = 0; mt < 2; mt++) {
            int r = mt * 16 + (lane >> 2);
            #pragma unroll
            for (int nt = 0; nt < 4; nt++) {
                int c = ncol + nt * 8 + (lane & 3) * 2;
                float v0 = acc[mt][nt][0], v1 = acc[mt][nt][1];
                float v2 = acc[mt][nt][2], v3 = acc[mt][nt][3];
                if (isquery) {
                    float s0 = sdiag[r] + smax[r];
                    float s1 = sdiag[r+8] + smax[r+8];
                    v0 = RATIO * (__expf(v0 - s0) + KEPS);
                    v1 = RATIO * (__expf(v1 - s0) + KEPS);
                    v2 = RATIO * (__expf(v2 - s1) + KEPS);
                    v3 = RATIO * (__expf(v3 - s1) + KEPS);
                    __half2 p0 = __floats2half2_rn(v0, v1);
                    __half2 p1 = __floats2half2_rn(v2, v3);
                    *(uint32_t*)(outh + ((size_t)bh * SEQ + n0 + r) * MF + c)     = *(uint32_t*)&p0;
                    *(uint32_t*)(outh + ((size_t)bh * SEQ + n0 + r + 8) * MF + c) = *(uint32_t*)&p1;
                } else {
                    float2 w0 = {v0, v1}, w1 = {v2, v3};
                    *(float2*)(outp + ((size_t)bh * SEQ + n0 + r) * MF + c)     = w0;
                    *(float2*)(outp + ((size_t)bh * SEQ + n0 + r + 8) * MF + c) = w1;
                }
            }
        }
        __syncthreads();
    }
}

// ---------------- kv + ksum (tf32, unchanged) ----------------
#define KAS_OFF 0
#define KVS_OFF 40960
#define KSR_OFF 50176
#define KV_SMEM 54272

extern "C" __global__ __launch_bounds__(256) void kv_ksum_kernel(
    const float* __restrict__ Kraw, const float* __restrict__ V, int ldv)
{
    extern __shared__ unsigned char ksm[];
    float (*As)[256][20] = (float(*)[256][20])(ksm + KAS_OFF);
    float (*Vs)[16][72]  = (float(*)[16][72])(ksm + KVS_OFF);
    float (*sred)[256]   = (float(*)[256])(ksm + KSR_OFF);

    int bh = blockIdx.y, chunk = blockIdx.x;
    int b = bh >> 4, h = bh & 15;
    int tid = threadIdx.x, lane = tid & 31, wid = tid >> 5;
    int wm = wid & 3, wn = wid >> 2;

    float kmax = g_kmax[bh];
    const float* Kb  = Kraw + ((size_t)bh * SEQ + chunk * 512) * MF;
    const float* Vb  = V + ((size_t)(b * SEQ + chunk * 512)) * ldv + h * HD;
    const float* dgb = g_kdiag + (size_t)bh * SEQ + chunk * 512;

    int mcol = tid & 63;
    int nr   = tid >> 6;
    float ks[4] = {0.f, 0.f, 0.f, 0.f};

    float acc[4][4][4];
    #pragma unroll
    for (int i = 0; i < 4; i++)
        #pragma unroll
        for (int j = 0; j < 4; j++)
            #pragma unroll
            for (int l = 0; l < 4; l++) acc[i][j][l] = 0.f;

#define LOAD_TILE(nt, buf)                                                        \
    {                                                                             \
        _Pragma("unroll")                                                         \
        for (int p = 0; p < 4; p++) {                                             \
            int nl = p * 4 + nr;                                                  \
            int ng = (nt) * 16 + nl;                                              \
            float dg = dgb[ng] + kmax;                                            \
            const float* kr = Kb + (size_t)ng * MF + mcol;                        \
            float r0 = kr[0], r1 = kr[64], r2 = kr[128], r3 = kr[192];            \
            float e0 = trunctf(RATIO * (__expf(r0 - dg) + KEPS));                 \
            float e1 = trunctf(RATIO * (__expf(r1 - dg) + KEPS));                 \
            float e2 = trunctf(RATIO * (__expf(r2 - dg) + KEPS));                 \
            float e3 = trunctf(RATIO * (__expf(r3 - dg) + KEPS));                 \
            ks[0] += e0; ks[1] += e1; ks[2] += e2; ks[3] += e3;                   \
            As[buf][mcol][nl] = e0;   As[buf][mcol+64][nl] = e1;                  \
            As[buf][mcol+128][nl] = e2; As[buf][mcol+192][nl] = e3;               \
        }                                                                         \
        cpasync16(&Vs[buf][tid >> 4][(tid & 15) * 4],                             \
                  Vb + (size_t)((nt) * 16 + (tid >> 4)) * ldv + (tid & 15) * 4);  \
        cpcommit();                                                               \
    }

    LOAD_TILE(0, 0);

    for (int nt = 0; nt < 32; nt++) {
        int buf = nt & 1;
        cpwait0();
        __syncthreads();
        if (nt + 1 < 32) LOAD_TILE(nt + 1, buf ^ 1);

        const uint32_t (*Au)[20] = (const uint32_t(*)[20])As[buf];
        const uint32_t (*Vu)[72] = (const uint32_t(*)[72])Vs[buf];

        #pragma unroll
        for (int ks2 = 0; ks2 < 2; ks2++) {
            int k0 = ks2 * 8;
            uint32_t a[4][4];
            #pragma unroll
            for (int mt = 0; mt < 4; mt++) {
                int r = wm * 64 + mt * 16 + (lane >> 2), c = k0 + (lane & 3);
                a[mt][0] = Au[r][c];
                a[mt][1] = Au[r+8][c];
                a[mt][2] = Au[r][c+4];
                a[mt][3] = Au[r+8][c+4];
            }
            uint32_t bb[4][2];
            #pragma unroll
            for (int dt = 0; dt < 4; dt++) {
                int n = wn * 32 + dt * 8 + (lane >> 2), kk = k0 + (lane & 3);
                bb[dt][0] = Vu[kk][n];
                bb[dt][1] = Vu[kk+4][n];
            }
            #pragma unroll
            for (int mt = 0; mt < 4; mt++)
                #pragma unroll
                for (int dt = 0; dt < 4; dt++)
                    mma16n8k8(acc[mt][dt], a[mt], bb[dt]);
        }
    }
#undef LOAD_TILE

    float* kvp = g_kvpart + ((size_t)(bh * NCHUNK + chunk)) * MF * HD;
    #pragma unroll
    for (int mt = 0; mt < 4; mt++) {
        int m = wm * 64 + mt * 16 + (lane >> 2);
        #pragma unroll
        for (int dt = 0; dt < 4; dt++) {
            int d = wn * 32 + dt * 8 + (lane & 3) * 2;
            float2 w0 = {acc[mt][dt][0], acc[mt][dt][1]};
            float2 w1 = {acc[mt][dt][2], acc[mt][dt][3]};
            *(float2*)(kvp + (size_t)m * HD + d)       = w0;
            *(float2*)(kvp + (size_t)(m + 8) * HD + d) = w1;
        }
    }
    __syncthreads();
    sred[nr][mcol]       = ks[0];
    sred[nr][mcol + 64]  = ks[1];
    sred[nr][mcol + 128] = ks[2];
    sred[nr][mcol + 192] = ks[3];
    __syncthreads();
    float s = sred[0][tid & 255] + sred[1][tid & 255] + sred[2][tid & 255] + sred[3][tid & 255];
    g_kspart[(size_t)(bh * NCHUNK + chunk) * MF + tid] = s;
}

// ---------------- reduce partials -> fp16 kvT + fp32 ksum ----------------
__global__ __launch_bounds__(256) void kv_reduce() {
    int bh = blockIdx.x, tid = threadIdx.x;
    for (int i = tid; i < MF * HD; i += 256) {
        float s = 0.f;
        #pragma unroll
        for (int c = 0; c < NCHUNK; c++)
            s += g_kvpart[((size_t)(bh * NCHUNK + c)) * MF * HD + i];
        int m = i / HD, d = i % HD;
        g_kvT16[((size_t)bh * HD + d) * MF + m] = __float2half_rn(s);
    }
    float s = 0.f;
    #pragma unroll
    for (int c = 0; c < NCHUNK; c++)
        s += g_kspart[(size_t)(bh * NCHUNK + c) * MF + tid];
    g_ksum[bh * MF + tid] = s;
}

// ---------------- attn fp16: out = (Qp16 @ kvT16^T) / (Qp16 . ksum), writes a16 ----------------
#define AT_A 0
#define AT_B 8192
#define AT_STAGE 12288
#define ATTN_SMEM (3*AT_STAGE)

__global__ __launch_bounds__(256) void attn_fp16(
    const __half* __restrict__ Qp, __half* __restrict__ outh)
{
    extern __shared__ char asm_[];
    uint32_t sb = (uint32_t)__cvta_generic_to_shared(asm_);
    __shared__ float sk[256];
    __shared__ float sdn[128];

    int bh = blockIdx.y, b = bh >> 4, h = bh & 15;
    int n0 = blockIdx.x * 128;
    int tid = threadIdx.x, lane = tid & 31, wid = tid >> 5;
    int wm = wid & 3, wn = wid >> 2;   // 4 x 2, warp tile 32x32

    sk[tid] = g_ksum[bh * MF + tid];
    if (tid < 128) sdn[tid] = 0.f;

    const __half* Qb = Qp + ((size_t)bh * SEQ + n0) * MF;
    const __half* Bb = g_kvT16 + (size_t)bh * HD * MF;

    int aR = wm * 32 + (lane & 15);
    int aKh = lane >> 4;
    int bN  = wn * 32 + (lane & 7) + ((lane >> 4) & 1) * 8;
    int bKh = (lane >> 3) & 1;

    float acc[2][4][4];
    #pragma unroll
    for (int i = 0; i < 2; i++)
        #pragma unroll
        for (int j = 0; j < 4; j++)
            #pragma unroll
            for (int l = 0; l < 4; l++) acc[i][j][l] = 0.f;
    float dn = 0.f;

#define AT_LOAD(kt, st)                                                            \
    {                                                                              \
        uint32_t stb = sb + (st) * AT_STAGE;                                       \
        int kc = (kt) * 32;                                                        \
        _Pragma("unroll")                                                          \
        for (int i = 0; i < 2; i++) {                                              \
            int row = (tid >> 2) + i * 64;                                         \
            int c = tid & 3;                                                       \
            uint32_t so = (uint32_t)(row * 64 + ((c ^ ((row >> 1) & 3)) << 4));    \
            cpasync16a(stb + AT_A + so, Qb + (size_t)row * MF + kc + c * 8);       \
        }                                                                          \
        {                                                                          \
            int d = tid >> 2, c = tid & 3;                                         \
            uint32_t so = (uint32_t)(d * 64 + ((c ^ ((d >> 1) & 3)) << 4));        \
            if (d < 64) cpasync16a(stb + AT_B + so, Bb + (size_t)d * MF + kc + c * 8); \
        }                                                                          \
    }

    AT_LOAD(0, 0); cpcommit();
    AT_LOAD(1, 1); cpcommit();

    for (int kt = 0; kt < 8; kt++) {
        int cur = kt % 3;
        cpwait1();
        __syncthreads();

        if (kt + 2 < 8) AT_LOAD(kt + 2, (kt + 2) % 3);
        cpcommit();

        uint32_t stb = sb + cur * AT_STAGE;

        // denominator from the SAME fp16 Qp values (tid<128 handles local row tid)
        if (tid < 128) {
            #pragma unroll
            for (int c = 0; c < 4; c++) {
                uint32_t off = (uint32_t)(tid * 64 + ((c ^ ((tid >> 1) & 3)) << 4));
                uint4 q = *(const uint4*)(asm_ + cur * AT_STAGE + AT_A + off);
                const float* skb = sk + kt * 32 + c * 8;
                float2 f0 = __half22float2(*(__half2*)&q.x);
                float2 f1 = __half22float2(*(__half2*)&q.y);
                float2 f2 = __half22float2(*(__half2*)&q.z);
                float2 f3 = __half22float2(*(__half2*)&q.w);
                dn += f0.x*skb[0] + f0.y*skb[1] + f1.x*skb[2] + f1.y*skb[3]
                    + f2.x*skb[4] + f2.y*skb[5] + f3.x*skb[6] + f3.y*skb[7];
            }
        }

        #pragma unroll
        for (int kh = 0; kh < 2; kh++) {
            int kc0 = kh * 2;
            uint32_t af[2][4], bf[2][4];
            #pragma unroll
            for (int am = 0; am < 2; am++) {
                int r = aR + am * 16;
                ldsm4(af[am], stb + AT_A + (uint32_t)(r * 64 + ((((kc0 + aKh) ^ ((r >> 1) & 3))) << 4)));
            }
            #pragma unroll
            for (int p = 0; p < 2; p++) {
                int n = bN + p * 16;
                ldsm4(bf[p], stb + AT_B + (uint32_t)(n * 64 + ((((kc0 + bKh) ^ ((n >> 1) & 3))) << 4)));
            }
            #pragma unroll
            for (int am = 0; am < 2; am++)
                #pragma unroll
                for (int t = 0; t < 4; t++)
                    mma_f16(acc[am][t], af[am], &bf[t >> 1][2 * (t & 1)]);
        }
    }
#undef AT_LOAD

    if (tid < 128) sdn[tid] = dn;
    __syncthreads();

    #pragma unroll
    for (int am = 0; am < 2; am++) {
        int rl = wm * 32 + am * 16 + (lane >> 2);
        float i0 = 1.f / sdn[rl];
        float i1 = 1.f / sdn[rl + 8];
        int r = n0 + rl;
        #pragma unroll
        for (int t = 0; t < 4; t++) {
            int c = wn * 32 + t * 8 + (lane & 3) * 2;
            __half2 p0 = __floats2half2_rn(acc[am][t][0] * i0, acc[am][t][1] * i0);
            __half2 p1 = __floats2half2_rn(acc[am][t][2] * i1, acc[am][t][3] * i1);
            *(uint32_t*)(outh + ((size_t)(b * SEQ + r)) * DMODEL + h * HD + c)       = *(uint32_t*)&p0;
            *(uint32_t*)(outh + ((size_t)(b * SEQ + r + 8)) * DMODEL + h * HD + c)   = *(uint32_t*)&p1;
        }
    }
}

// ---------------- fused residual + LayerNorm (+optional fp16 copy) ----------------
__global__ __launch_bounds__(256) void ln_kernel(
    const float* __restrict__ a, const float* __restrict__ res,
    const float* __restrict__ gam, const float* __restrict__ bet,
    float* __restrict__ out, __half* __restrict__ out16)
{
    __shared__ float red[8];
    int row = blockIdx.x, tid = threadIdx.x;
    int lane = tid & 31, w = tid >> 5;
    size_t base = (size_t)row * DMODEL + tid * 4;
    float4 v = *(const float4*)(a + base);
    float4 r = *(const float4*)(res + base);
    v.x += r.x; v.y += r.y; v.z += r.z; v.w += r.w;

    float s = v.x + v.y + v.z + v.w;
    #pragma unroll
    for (int o = 16; o; o >>= 1) s += __shfl_xor_sync(0xffffffffu, s, o);
    if (lane == 0) red[w] = s;
    __syncthreads();
    float t = (tid < 8) ? red[tid] : 0.f;
    if (w == 0) {
        #pragma unroll
        for (int o = 4; o; o >>= 1) t += __shfl_xor_sync(0xffffffffu, t, o);
        if (lane == 0) red[0] = t;
    }
    __syncthreads();
    float mean = red[0] * (1.f / DMODEL);
    __syncthreads();

    float d0 = v.x - mean, d1 = v.y - mean, d2 = v.z - mean, d3 = v.w - mean;
    float s2 = d0*d0 + d1*d1 + d2*d2 + d3*d3;
    #pragma unroll
    for (int o = 16; o; o >>= 1) s2 += __shfl_xor_sync(0xffffffffu, s2, o);
    if (lane == 0) red[w] = s2;
    __syncthreads();
    float t2 = (tid < 8) ? red[tid] : 0.f;
    if (w == 0) {
        #pragma unroll
        for (int o = 4; o; o >>= 1) t2 += __shfl_xor_sync(0xffffffffu, t2, o);
        if (lane == 0) red[0] = t2;
    }
    __syncthreads();
    float var = red[0] * (1.f / DMODEL);
    float inv = rsqrtf(var + LNEPS);

    float4 g4 = *(const float4*)(gam + tid * 4);
    float4 b4 = *(const float4*)(bet + tid * 4);
    float4 o4;
    o4.x = d0 * inv * g4.x + b4.x;
    o4.y = d1 * inv * g4.y + b4.y;
    o4.z = d2 * inv * g4.z + b4.z;
    o4.w = d3 * inv * g4.w + b4.w;
    *(float4*)(out + base) = o4;
    if (out16) {
        __half2 p0 = __floats2half2_rn(o4.x, o4.y);
        __half2 p1 = __floats2half2_rn(o4.z, o4.w);
        uint2 u = {*(uint32_t*)&p0, *(uint32_t*)&p1};
        *(uint2*)(out16 + base) = u;
    }
}

// ---------------- launch ----------------
extern "C" void kernel_launch(void* const* d_in, const int* in_sizes, int n_in,
                              void* d_out, int out_size)
{
    const float* x  = (const float*)d_in[0];
    const float* wq = (const float*)d_in[1];  const float* bq = (const float*)d_in[2];
    const float* wk = (const float*)d_in[3];  const float* bk = (const float*)d_in[4];
    const float* wv = (const float*)d_in[5];  const float* bv = (const float*)d_in[6];
    const float* wo = (const float*)d_in[7];  const float* bo = (const float*)d_in[8];
    const float* proj = (const float*)d_in[9];
    const float* w1 = (const float*)d_in[10]; const float* b1 = (const float*)d_in[11];
    const float* w2 = (const float*)d_in[12]; const float* b2 = (const float*)d_in[13];
    const float* ln1g = (const float*)d_in[14]; const float* ln1b = (const float*)d_in[15];
    const float* ln2g = (const float*)d_in[16]; const float* ln2b = (const float*)d_in[17];
    float* out = (float*)d_out;

    static int attr_done = 0;
    if (!attr_done) {
        cudaFuncSetAttribute(fp16_gemm, cudaFuncAttributeMaxDynamicSharedMemorySize, GEMM_SMEM);
        cudaFuncSetAttribute(dash_fused, cudaFuncAttributeMaxDynamicSharedMemorySize, DASH_SMEM);
        cudaFuncSetAttribute(kv_ksum_kernel, cudaFuncAttributeMaxDynamicSharedMemorySize, KV_SMEM);
        cudaFuncSetAttribute(attn_fp16, cudaFuncAttributeMaxDynamicSharedMemorySize, ATTN_SMEM);
        attr_done = 1;
    }

    float *QKV, *bqkv, *Kp, *kdiag, *kmax, *x1, *t;
    cudaGetSymbolAddress((void**)&QKV, g_QKV);
    cudaGetSymbolAddress((void**)&bqkv, g_bqkv);
    cudaGetSymbolAddress((void**)&Kp, g_Kp);
    cudaGetSymbolAddress((void**)&kdiag, g_kdiag);
    cudaGetSymbolAddress((void**)&kmax, g_kmax);
    cudaGetSymbolAddress((void**)&x1, g_x1);
    cudaGetSymbolAddress((void**)&t,  g_t);

    __half *Qp16, *x16, *a16, *x116, *h16, *wqkvT16, *woT16, *w1T16, *w2T16;
    cudaGetSymbolAddress((void**)&Qp16, g_Qp16);
    cudaGetSymbolAddress((void**)&x16, g_x16);
    cudaGetSymbolAddress((void**)&a16, g_a16);
    cudaGetSymbolAddress((void**)&x116, g_x116);
    cudaGetSymbolAddress((void**)&h16, g_h16);
    cudaGetSymbolAddress((void**)&wqkvT16, g_wqkvT16);
    cudaGetSymbolAddress((void**)&woT16, g_woT16);
    cudaGetSymbolAddress((void**)&w1T16, g_w1T16);
    cudaGetSymbolAddress((void**)&w2T16, g_w2T16);

    prep_proj<<<64, 256>>>(proj);
    kmax_init<<<1, 64>>>();
    pack_bias<<<4, 256>>>(bq, bk, bv);

    wt_conv_h<<<dim3(32, 32), 256>>>(wq, wqkvT16,               DMODEL, DMODEL);
    wt_conv_h<<<dim3(32, 32), 256>>>(wk, wqkvT16 + 1024*1024,   DMODEL, DMODEL);
    wt_conv_h<<<dim3(32, 32), 256>>>(wv, wqkvT16 + 2*1024*1024, DMODEL, DMODEL);
    wt_conv_h<<<dim3(32, 32), 256>>>(wo, woT16, DMODEL, DMODEL);
    wt_conv_h<<<dim3(DFF/32, DMODEL/32), 256>>>(w1, w1T16, DMODEL, DFF);
    wt_conv_h<<<dim3(DMODEL/32, DFF/32), 256>>>(w2, w2T16, DFF, DMODEL);
    conv_act_h<<<ROWS*DMODEL/4/256, 256>>>(x, x16, ROWS*DMODEL/4);

    fp16_gemm<<<dim3(D3/128, ROWS/128), 256, GEMM_SMEM>>>(
        x16, wqkvT16, bqkv, QKV, nullptr, ROWS, D3, DMODEL, 0);

    dim3 gdash(SEQ/128, BH);
    dash_fused<<<gdash, 256, DASH_SMEM>>>(QKV, D3, nullptr, Qp16, nullptr, nullptr, 1);
    dash_fused<<<gdash, 256, DASH_SMEM>>>(QKV + 1024, D3, Kp, nullptr, kdiag, kmax, 0);

    kv_ksum_kernel<<<dim3(NCHUNK, BH), 256, KV_SMEM>>>(Kp, QKV + 2048, D3);
    kv_reduce<<<BH, 256>>>();
    attn_fp16<<<dim3(SEQ/128, BH), 256, ATTN_SMEM>>>(Qp16, a16);

    fp16_gemm<<<dim3(DMODEL/128, ROWS/128), 256, GEMM_SMEM>>>(
        a16, woT16, bo, t, nullptr, ROWS, DMODEL, DMODEL, 0);
    ln_kernel<<<ROWS, 256>>>(t, x, ln1g, ln1b, x1, x116);

    fp16_gemm<<<dim3(DFF/128, ROWS/128), 256, GEMM_SMEM>>>(
        x116, w1T16, b1, nullptr, h16, ROWS, DFF, DMODEL, 1);
    fp16_gemm<<<dim3(DMODEL/128, ROWS/128), 256, GEMM_SMEM>>>(
        h16, w2T16, b2, t, nullptr, ROWS, DMODEL, DFF, 0);
    ln_kernel<<<ROWS, 256>>>(t, x1, ln2g, ln2b, out, nullptr);
}